// round 5
// baseline (speedup 1.0000x reference)
#include <cuda_runtime.h>
#include <math.h>

#define BATCH 16
#define NSAMP 72000
#define TOTF  2039   // 17+33+65+129+257+513+1025

__device__ double g_s1[TOTF];
__device__ double g_s2[TOTF];

__host__ __device__ constexpr int ilog2c(int n) { return (n <= 1) ? 0 : 1 + ilog2c(n >> 1); }

// Blocks runtime constant folding while preserving exact double bits.
__device__ __forceinline__ double opaque_d(double x) { volatile double t = x; return t; }

__device__ __forceinline__ float2 cadd(float2 a, float2 b) { return make_float2(a.x + b.x, a.y + b.y); }
__device__ __forceinline__ float2 csub(float2 a, float2 b) { return make_float2(a.x - b.x, a.y - b.y); }
__device__ __forceinline__ float2 cmul(float2 a, float2 b) {
    return make_float2(a.x * b.x - a.y * b.y, a.x * b.y + a.y * b.x);
}

// Packed complex FFT (z = x + i*x_hat) over all frames of one scale.
// Radix-4 (fused 2x radix-2) stages; first two stages fused into the windowed
// load; leftover radix-2 stage for odd log2(N). XOR bank swizzle on buf.
// TPF is chosen so each thread owns ~4 independent butterflies per stage
// (BPT4=4) -> in-warp MLP hides LDS latency (issue-bound fix, R4 ncu).
template<int NFFT, int OFF>
__global__ void __launch_bounds__(256)
stft_kernel(const float* __restrict__ x, const float* __restrict__ xh) {
    constexpr int HOP   = NFFT / 4;
    constexpr int PAD   = NFFT / 2;
    constexpr int T     = 1 + NSAMP / HOP;
    constexpr int TOTAL = BATCH * T;
    constexpr int F     = NFFT / 2 + 1;
    constexpr int LOG2N = ilog2c(NFFT);
    constexpr int TPB   = 256;
    constexpr int Q     = NFFT / 4;                    // radix-4 butterflies per frame
    // FPB chosen for BPT4=4 (BUFSZ=4096 -> 32KB); N=2048 capped to fit 48KB static smem.
    constexpr int FPB   = (NFFT >= 2048) ? 1 : (4096 / NFFT);
    constexpr int TPF   = TPB / FPB;                   // threads per frame
    constexpr int BPT4  = Q / TPF;                     // fused butterflies per thread (4; 2 @2048)
    constexpr int KPT   = (F + TPF - 1) / TPF;         // freq bins per thread (unpack)
    constexpr int BUFSZ = FPB * NFFT;
    constexpr int S     = ilog2c(BUFSZ) - 4;

    __shared__ float2 buf[BUFSZ];
    __shared__ float2 tw[NFFT / 2];
    __shared__ float  win[NFFT];
    __shared__ float  red1[F];
    __shared__ float  red2[F];

    const int tid  = threadIdx.x;
    const int slot = tid / TPF;
    const int ltid = tid % TPF;

    // Bank swizzle: bijective (modifies only bits 0-3 by a function of bits>=4).
    auto sw = [](int i) { return i ^ (((i >> S) ^ (i >> 4)) & 15); };

    // Twiddles: tw[t] = exp(-2*pi*i*t/N). Window: periodic hann / sqrt(0.375*N).
    const float rnorm = rsqrtf(0.375f * (float)NFFT);
    for (int t = tid; t < NFFT / 2; t += TPB) {
        float s, c;
        sincospif(2.0f * (float)t / (float)NFFT, &s, &c);
        tw[t] = make_float2(c, -s);
    }
    for (int t = tid; t < NFFT; t += TPB) {
        win[t] = (0.5f - 0.5f * cospif(2.0f * (float)t / (float)NFFT)) * rnorm;
    }
    for (int t = tid; t < F; t += TPB) { red1[t] = 0.0f; red2[t] = 0.0f; }

    float acc1[KPT], acc2[KPT];
#pragma unroll
    for (int r = 0; r < KPT; r++) { acc1[r] = 0.0f; acc2[r] = 0.0f; }

    __syncthreads();

    for (int base = blockIdx.x * FPB; base < TOTAL; base += gridDim.x * FPB) {
        const int gf = base + slot;
        const bool valid = (gf < TOTAL);

        // Load + window + first fused radix-4 stage (stages len=2,4; twiddles = 1).
        if (valid) {
            const int b  = gf / T;
            const int t0 = gf - b * T;
            const int start = t0 * HOP - PAD;
            const float* xb  = x  + b * NSAMP;
            const float* xhb = xh + b * NSAMP;
#pragma unroll
            for (int r = 0; r < BPT4; r++) {
                const int idx = ltid + r * TPF;                       // [0, N/4)
                const int g   = (int)(__brev((unsigned)idx) >> (32 - (LOG2N - 2)));
                float2 a[4];
                constexpr int offs4[4] = {0, NFFT / 2, NFFT / 4, 3 * NFFT / 4};
#pragma unroll
                for (int k = 0; k < 4; k++) {
                    const int tt = idx + offs4[k];
                    int s = start + tt;
                    s = (s < 0) ? -s : s;                        // reflect left
                    s = (s >= NSAMP) ? (2 * NSAMP - 2 - s) : s;  // reflect right
                    const float wv = win[tt];
                    a[k] = make_float2(xb[s] * wv, xhb[s] * wv);
                }
                const float2 c0 = cadd(a[0], a[1]), c1 = csub(a[0], a[1]);
                const float2 c2 = cadd(a[2], a[3]), c3 = csub(a[2], a[3]);
                const int wb = slot * NFFT + 4 * g;
                buf[sw(wb + 0)] = cadd(c0, c2);
                buf[sw(wb + 2)] = csub(c0, c2);
                buf[sw(wb + 1)] = make_float2(c1.x + c3.y, c1.y - c3.x);  // c1 - i*c3
                buf[sw(wb + 3)] = make_float2(c1.x - c3.y, c1.y + c3.x);  // c1 + i*c3
            }
        }
        __syncthreads();

        // Fused radix-4 stages: pair (len=L, len=2L) for L = 8, 32, 128, 512...
#pragma unroll
        for (int L = 8; 2 * L <= NFFT; L *= 4) {
#pragma unroll
            for (int r = 0; r < BPT4; r++) {
                const int idx = ltid + r * TPF;              // [0, N/4)
                const int j   = idx & (L / 2 - 1);
                const int g   = idx / (L / 2);
                const int p   = slot * NFFT + g * (2 * L) + j;
                float2 a0 = buf[sw(p)];
                float2 a1 = buf[sw(p + L / 2)];
                float2 a2 = buf[sw(p + L)];
                float2 a3 = buf[sw(p + 3 * L / 2)];
                const float2 t1 = tw[j * (NFFT / L)];        // w_L^j
                const float2 t2 = tw[j * (NFFT / (2 * L))];  // w_{2L}^j
                const float2 u1 = cmul(t1, a1), u3 = cmul(t1, a3);
                const float2 c0 = cadd(a0, u1), c1 = csub(a0, u1);
                const float2 c2 = cadd(a2, u3), c3 = csub(a2, u3);
                const float2 v2 = cmul(t2, c2), v3 = cmul(t2, c3);
                buf[sw(p)]             = cadd(c0, v2);
                buf[sw(p + L)]         = csub(c0, v2);
                buf[sw(p + L / 2)]     = make_float2(c1.x + v3.y, c1.y - v3.x);  // c1 - i*v3
                buf[sw(p + 3 * L / 2)] = make_float2(c1.x - v3.y, c1.y + v3.x);  // c1 + i*v3
            }
            __syncthreads();
        }

        // Leftover radix-2 stage (len = N) for odd log2(N).
        if constexpr (LOG2N & 1) {
#pragma unroll
            for (int r = 0; r < 2 * BPT4; r++) {
                const int idx = ltid + r * TPF;              // [0, N/2)
                const int p = slot * NFFT + idx;
                const float2 a  = buf[sw(p)];
                const float2 b2 = buf[sw(p + NFFT / 2)];
                const float2 t  = cmul(tw[idx], b2);
                buf[sw(p)]            = cadd(a, t);
                buf[sw(p + NFFT / 2)] = csub(a, t);
            }
            __syncthreads();
        }

        // Unpack X (from x) and Xh (from x_hat), accumulate stats
        if (valid) {
#pragma unroll
            for (int r = 0; r < KPT; r++) {
                const int k = ltid + r * TPF;
                if (k <= NFFT / 2) {
                    const float2 zk = buf[sw(slot * NFFT + k)];
                    const float2 zn = buf[sw(slot * NFFT + ((NFFT - k) & (NFFT - 1)))];
                    const float ar = 0.5f * (zk.x + zn.x);
                    const float ai = 0.5f * (zk.y - zn.y);
                    const float br = 0.5f * (zk.y + zn.y);
                    const float bi = 0.5f * (zn.x - zk.x);
                    const float magA = sqrtf(ar * ar + ai * ai);
                    const float magB = sqrtf(br * br + bi * bi);
                    const float d = magB - magA;          // |Xh| - |X|
                    acc1[r] += fabsf(d);
                    acc2[r] += d * d;
                }
            }
        }
        __syncthreads();   // protect buf before next load
    }

    // Block reduce: registers -> shared float
#pragma unroll
    for (int r = 0; r < KPT; r++) {
        const int k = ltid + r * TPF;
        if (k <= NFFT / 2) {
            atomicAdd(&red1[k], acc1[r]);
            atomicAdd(&red2[k], acc2[r]);
        }
    }
    __syncthreads();

    for (int k = tid; k < F; k += TPB) {
        atomicAdd(&g_s1[OFF + k], (double)red1[k]);
        atomicAdd(&g_s2[OFF + k], (double)red2[k]);
    }
}

// Mel-band combine. One thread per (scale, band-candidate). Band m support =
// bins f with f_pts[m] < f*step < f_pts[m+2] (strict). All interior decisions
// have >=1e-3 relative margins (safe in double). The ONLY knife-edge is the
// Nyquist bin (freq == 12000.0 exactly) vs f_pts[65] (a log10/pow round-trip
// of 12000, = 12000 +- few ulp, libm-rounding dependent). We reproduce the
// libdevice decision and take the OPPOSITE (matches numpy; verified rel_err=0).
__global__ void loss_kernel(float* out) {
    __shared__ int    nb[7];
    __shared__ double sl[7];
    const int tid = threadIdx.x;
    if (tid < 7) { nb[tid] = 0; sl[tid] = 0.0; }
    __syncthreads();

    const int scale = tid >> 6;
    const int m     = tid & 63;

    if (scale < 7) {
        const int offs[7] = {0, 17, 50, 115, 244, 501, 1014};
        const int Ts[7]   = {9001, 4501, 2251, 1126, 563, 282, 141};
        const int nfft = 32 << scale;
        const int F = nfft / 2 + 1;
        const double step = 12000.0 / (double)(F - 1);
        const double melmax = 2595.0 * log10(1.0 + 12000.0 / 700.0);

        const double e65  = (melmax * 65.0 / 65.0) / 2595.0;
        const double hi65 = 700.0 * (pow(10.0, opaque_d(e65)) - 1.0);
        const bool   nyq_in = !(hi65 > 12000.0);

        int a[2], b[2];   // [0] = band m, [1] = band m-1
        for (int q = 0; q < 2; q++) {
            const int mm = m - q;
            if (mm < 0) { a[q] = 0; b[q] = 0; continue; }
            const double lo = 700.0 * (pow(10.0, opaque_d(melmax * (double)mm / 65.0) / 2595.0) - 1.0);
            int a0 = (int)floor(lo / step); if ((double)a0 * step <= lo) a0++;  // first f: f*step > lo
            if (a0 < 0) a0 = 0;
            int b0;
            if (mm + 2 == 65) {
                b0 = nyq_in ? F : (F - 1);
            } else {
                const double hi = 700.0 * (pow(10.0, opaque_d(melmax * (double)(mm + 2) / 65.0) / 2595.0) - 1.0);
                b0 = (int)floor(hi / step); if ((double)b0 * step <  hi) b0++;  // last f+1: f*step < hi
                if (b0 > F) b0 = F;
            }
            a[q] = a0; b[q] = b0;
        }
        const bool nonempty = (b[0] > a[0]);
        const bool dup = (m > 0) && (a[0] == a[1]) && (b[0] == b[1]) && nonempty;
        if (nonempty && !dup) {
            atomicAdd(&nb[scale], 1);
            double s1 = 0.0, s2 = 0.0;
            for (int f = a[0]; f < b[0]; f++) {
                s1 += g_s1[offs[scale] + f];
                s2 += g_s2[offs[scale] + f];
            }
            const double cnt = (double)(b[0] - a[0]) * (double)BATCH * (double)Ts[scale];
            const double val = s1 / cnt + sqrt(s2 / cnt + 1e-8);
            atomicAdd(&sl[scale], val);
        }
    }
    __syncthreads();

    if (tid == 0) {
        double tot = 0.0;
        for (int s = 0; s < 7; s++) tot += sl[s] / (double)nb[s];
        out[0] = (float)(tot / 7.0);
    }
}

extern "C" void kernel_launch(void* const* d_in, const int* in_sizes, int n_in,
                              void* d_out, int out_size) {
    const float* xh = (const float*)d_in[0];   // x_hat
    const float* x  = (const float*)d_in[1];   // x

    void *p1 = nullptr, *p2 = nullptr;
    cudaGetSymbolAddress(&p1, g_s1);
    cudaGetSymbolAddress(&p2, g_s2);
    cudaMemsetAsync(p1, 0, TOTF * sizeof(double));
    cudaMemsetAsync(p2, 0, TOTF * sizeof(double));

    stft_kernel<  32,    0><<<740, 256>>>(x, xh);
    stft_kernel<  64,   17><<<740, 256>>>(x, xh);
    stft_kernel< 128,   50><<<740, 256>>>(x, xh);
    stft_kernel< 256,  115><<<740, 256>>>(x, xh);
    stft_kernel< 512,  244><<<740, 256>>>(x, xh);
    stft_kernel<1024,  501><<<740, 256>>>(x, xh);
    stft_kernel<2048, 1014><<<740, 256>>>(x, xh);

    loss_kernel<<<1, 512>>>((float*)d_out);
}

// round 6
// speedup vs baseline: 1.3369x; 1.3369x over previous
#include <cuda_runtime.h>
#include <math.h>

#define BATCH 16
#define NSAMP 72000
#define TOTF  2039   // 17+33+65+129+257+513+1025

__device__ double g_s1[TOTF];
__device__ double g_s2[TOTF];

__host__ __device__ constexpr int ilog2c(int n) { return (n <= 1) ? 0 : 1 + ilog2c(n >> 1); }

// Blocks runtime constant folding while preserving exact double bits.
__device__ __forceinline__ double opaque_d(double x) { volatile double t = x; return t; }

__device__ __forceinline__ float2 cadd(float2 a, float2 b) { return make_float2(a.x + b.x, a.y + b.y); }
__device__ __forceinline__ float2 csub(float2 a, float2 b) { return make_float2(a.x - b.x, a.y - b.y); }
__device__ __forceinline__ float2 cmul(float2 a, float2 b) {
    return make_float2(a.x * b.x - a.y * b.y, a.x * b.y + a.y * b.x);
}

// Packed complex FFT (z = x + i*x_hat) over all frames of one scale.
// Radix-4 fused stages; first two stages fused into the windowed load;
// leftover radix-2 for odd log2(N). XOR bank swizzle on buf.
// TPF = NFFT/8 -> BPT4=2 (ILP) and, crucially, frame-scoped synchronization:
//   TPF<=32 : whole frame in ONE warp -> __syncwarp only, no block coupling
//   TPF=64/128: named barrier syncs only that frame's warps
//   TPF=256 : classic __syncthreads (N=2048 only)
template<int NFFT, int OFF>
__global__ void __launch_bounds__(256)
stft_kernel(const float* __restrict__ x, const float* __restrict__ xh) {
    constexpr int HOP   = NFFT / 4;
    constexpr int PAD   = NFFT / 2;
    constexpr int T     = 1 + NSAMP / HOP;
    constexpr int TOTAL = BATCH * T;
    constexpr int F     = NFFT / 2 + 1;
    constexpr int LOG2N = ilog2c(NFFT);
    constexpr int TPB   = 256;
    constexpr int Q     = NFFT / 4;                    // radix-4 butterflies per frame
    constexpr int TPF   = (NFFT / 8 > TPB) ? TPB : (NFFT / 8);  // threads per frame
    constexpr int FPB   = TPB / TPF;                   // frames per block
    constexpr int BPT4  = Q / TPF;                     // fused butterflies/thread (2)
    constexpr int KPT   = (F + TPF - 1) / TPF;         // freq bins per thread (unpack)
    constexpr int BUFSZ = FPB * NFFT;                  // 2048 complex = 16KB
    constexpr int S     = ilog2c(BUFSZ) - 4;

    __shared__ float2 buf[BUFSZ];
    __shared__ float2 tw[NFFT / 2];
    __shared__ float  win[NFFT];
    __shared__ float  red1[F];
    __shared__ float  red2[F];

    const int tid  = threadIdx.x;
    const int slot = tid / TPF;
    const int ltid = tid % TPF;

    // Bank swizzle: bijective (modifies only bits 0-3 by a function of bits>=4).
    auto sw = [](int i) { return i ^ (((i >> S) ^ (i >> 4)) & 15); };

    // Frame-scoped sync.
    auto fsync = [&]() {
        if constexpr (TPF <= 32) { __syncwarp(); }
        else if constexpr (TPF >= TPB) { __syncthreads(); }
        else { asm volatile("bar.sync %0, %1;" :: "r"(slot + 1), "r"(TPF) : "memory"); }
    };

    // Twiddles: tw[t] = exp(-2*pi*i*t/N). Window: periodic hann / sqrt(0.375*N).
    const float rnorm = rsqrtf(0.375f * (float)NFFT);
    for (int t = tid; t < NFFT / 2; t += TPB) {
        float s, c;
        sincospif(2.0f * (float)t / (float)NFFT, &s, &c);
        tw[t] = make_float2(c, -s);
    }
    for (int t = tid; t < NFFT; t += TPB) {
        win[t] = (0.5f - 0.5f * cospif(2.0f * (float)t / (float)NFFT)) * rnorm;
    }
    for (int t = tid; t < F; t += TPB) { red1[t] = 0.0f; red2[t] = 0.0f; }

    float acc1[KPT], acc2[KPT];
#pragma unroll
    for (int r = 0; r < KPT; r++) { acc1[r] = 0.0f; acc2[r] = 0.0f; }

    __syncthreads();

    for (int base = blockIdx.x * FPB; base < TOTAL; base += gridDim.x * FPB) {
        const int gf = base + slot;
        const bool valid = (gf < TOTAL);

        // Load + window + first fused radix-4 stage (stages len=2,4; twiddles = 1).
        if (valid) {
            const int b  = gf / T;
            const int t0 = gf - b * T;
            const int start = t0 * HOP - PAD;
            const float* xb  = x  + b * NSAMP;
            const float* xhb = xh + b * NSAMP;
#pragma unroll
            for (int r = 0; r < BPT4; r++) {
                const int idx = ltid + r * TPF;                       // [0, N/4)
                const int g   = (int)(__brev((unsigned)idx) >> (32 - (LOG2N - 2)));
                float2 a[4];
                constexpr int offs4[4] = {0, NFFT / 2, NFFT / 4, 3 * NFFT / 4};
#pragma unroll
                for (int k = 0; k < 4; k++) {
                    const int tt = idx + offs4[k];
                    int s = start + tt;
                    s = (s < 0) ? -s : s;                        // reflect left
                    s = (s >= NSAMP) ? (2 * NSAMP - 2 - s) : s;  // reflect right
                    const float wv = win[tt];
                    a[k] = make_float2(xb[s] * wv, xhb[s] * wv);
                }
                const float2 c0 = cadd(a[0], a[1]), c1 = csub(a[0], a[1]);
                const float2 c2 = cadd(a[2], a[3]), c3 = csub(a[2], a[3]);
                const int wb = slot * NFFT + 4 * g;
                buf[sw(wb + 0)] = cadd(c0, c2);
                buf[sw(wb + 2)] = csub(c0, c2);
                buf[sw(wb + 1)] = make_float2(c1.x + c3.y, c1.y - c3.x);  // c1 - i*c3
                buf[sw(wb + 3)] = make_float2(c1.x - c3.y, c1.y + c3.x);  // c1 + i*c3
            }
        }
        fsync();

        // Fused radix-4 stages: pair (len=L, len=2L) for L = 8, 32, 128, 512...
#pragma unroll
        for (int L = 8; 2 * L <= NFFT; L *= 4) {
#pragma unroll
            for (int r = 0; r < BPT4; r++) {
                const int idx = ltid + r * TPF;              // [0, N/4)
                const int j   = idx & (L / 2 - 1);
                const int g   = idx / (L / 2);
                const int p   = slot * NFFT + g * (2 * L) + j;
                float2 a0 = buf[sw(p)];
                float2 a1 = buf[sw(p + L / 2)];
                float2 a2 = buf[sw(p + L)];
                float2 a3 = buf[sw(p + 3 * L / 2)];
                const float2 t1 = tw[j * (NFFT / L)];        // w_L^j
                const float2 t2 = tw[j * (NFFT / (2 * L))];  // w_{2L}^j
                const float2 u1 = cmul(t1, a1), u3 = cmul(t1, a3);
                const float2 c0 = cadd(a0, u1), c1 = csub(a0, u1);
                const float2 c2 = cadd(a2, u3), c3 = csub(a2, u3);
                const float2 v2 = cmul(t2, c2), v3 = cmul(t2, c3);
                buf[sw(p)]             = cadd(c0, v2);
                buf[sw(p + L)]         = csub(c0, v2);
                buf[sw(p + L / 2)]     = make_float2(c1.x + v3.y, c1.y - v3.x);  // c1 - i*v3
                buf[sw(p + 3 * L / 2)] = make_float2(c1.x - v3.y, c1.y + v3.x);  // c1 + i*v3
            }
            fsync();
        }

        // Leftover radix-2 stage (len = N) for odd log2(N).
        if constexpr (LOG2N & 1) {
#pragma unroll
            for (int r = 0; r < 2 * BPT4; r++) {
                const int idx = ltid + r * TPF;              // [0, N/2)
                const int p = slot * NFFT + idx;
                const float2 a  = buf[sw(p)];
                const float2 b2 = buf[sw(p + NFFT / 2)];
                const float2 t  = cmul(tw[idx], b2);
                buf[sw(p)]            = cadd(a, t);
                buf[sw(p + NFFT / 2)] = csub(a, t);
            }
            fsync();
        }

        // Unpack X (from x) and Xh (from x_hat), accumulate stats
        if (valid) {
#pragma unroll
            for (int r = 0; r < KPT; r++) {
                const int k = ltid + r * TPF;
                if (k <= NFFT / 2) {
                    const float2 zk = buf[sw(slot * NFFT + k)];
                    const float2 zn = buf[sw(slot * NFFT + ((NFFT - k) & (NFFT - 1)))];
                    const float ar = 0.5f * (zk.x + zn.x);
                    const float ai = 0.5f * (zk.y - zn.y);
                    const float br = 0.5f * (zk.y + zn.y);
                    const float bi = 0.5f * (zn.x - zk.x);
                    const float magA = sqrtf(ar * ar + ai * ai);
                    const float magB = sqrtf(br * br + bi * bi);
                    const float d = magB - magA;          // |Xh| - |X|
                    acc1[r] += fabsf(d);
                    acc2[r] += d * d;
                }
            }
        }
        fsync();   // protect buf before next load (frame-scoped)
    }

    // Block reduce: registers -> shared float
#pragma unroll
    for (int r = 0; r < KPT; r++) {
        const int k = ltid + r * TPF;
        if (k <= NFFT / 2) {
            atomicAdd(&red1[k], acc1[r]);
            atomicAdd(&red2[k], acc2[r]);
        }
    }
    __syncthreads();

    for (int k = tid; k < F; k += TPB) {
        atomicAdd(&g_s1[OFF + k], (double)red1[k]);
        atomicAdd(&g_s2[OFF + k], (double)red2[k]);
    }
}

// Mel-band combine. One thread per (scale, band-candidate). Band m support =
// bins f with f_pts[m] < f*step < f_pts[m+2] (strict). All interior decisions
// have >=1e-3 relative margins (safe in double). The ONLY knife-edge is the
// Nyquist bin (freq == 12000.0 exactly) vs f_pts[65] (a log10/pow round-trip
// of 12000, = 12000 +- few ulp, libm-rounding dependent). We reproduce the
// libdevice decision and take the OPPOSITE (matches numpy; verified rel_err=0).
__global__ void loss_kernel(float* out) {
    __shared__ int    nb[7];
    __shared__ double sl[7];
    const int tid = threadIdx.x;
    if (tid < 7) { nb[tid] = 0; sl[tid] = 0.0; }
    __syncthreads();

    const int scale = tid >> 6;
    const int m     = tid & 63;

    if (scale < 7) {
        const int offs[7] = {0, 17, 50, 115, 244, 501, 1014};
        const int Ts[7]   = {9001, 4501, 2251, 1126, 563, 282, 141};
        const int nfft = 32 << scale;
        const int F = nfft / 2 + 1;
        const double step = 12000.0 / (double)(F - 1);
        const double melmax = 2595.0 * log10(1.0 + 12000.0 / 700.0);

        const double e65  = (melmax * 65.0 / 65.0) / 2595.0;
        const double hi65 = 700.0 * (pow(10.0, opaque_d(e65)) - 1.0);
        const bool   nyq_in = !(hi65 > 12000.0);

        int a[2], b[2];   // [0] = band m, [1] = band m-1
        for (int q = 0; q < 2; q++) {
            const int mm = m - q;
            if (mm < 0) { a[q] = 0; b[q] = 0; continue; }
            const double lo = 700.0 * (pow(10.0, opaque_d(melmax * (double)mm / 65.0) / 2595.0) - 1.0);
            int a0 = (int)floor(lo / step); if ((double)a0 * step <= lo) a0++;  // first f: f*step > lo
            if (a0 < 0) a0 = 0;
            int b0;
            if (mm + 2 == 65) {
                b0 = nyq_in ? F : (F - 1);
            } else {
                const double hi = 700.0 * (pow(10.0, opaque_d(melmax * (double)(mm + 2) / 65.0) / 2595.0) - 1.0);
                b0 = (int)floor(hi / step); if ((double)b0 * step <  hi) b0++;  // last f+1: f*step < hi
                if (b0 > F) b0 = F;
            }
            a[q] = a0; b[q] = b0;
        }
        const bool nonempty = (b[0] > a[0]);
        const bool dup = (m > 0) && (a[0] == a[1]) && (b[0] == b[1]) && nonempty;
        if (nonempty && !dup) {
            atomicAdd(&nb[scale], 1);
            double s1 = 0.0, s2 = 0.0;
            for (int f = a[0]; f < b[0]; f++) {
                s1 += g_s1[offs[scale] + f];
                s2 += g_s2[offs[scale] + f];
            }
            const double cnt = (double)(b[0] - a[0]) * (double)BATCH * (double)Ts[scale];
            const double val = s1 / cnt + sqrt(s2 / cnt + 1e-8);
            atomicAdd(&sl[scale], val);
        }
    }
    __syncthreads();

    if (tid == 0) {
        double tot = 0.0;
        for (int s = 0; s < 7; s++) tot += sl[s] / (double)nb[s];
        out[0] = (float)(tot / 7.0);
    }
}

extern "C" void kernel_launch(void* const* d_in, const int* in_sizes, int n_in,
                              void* d_out, int out_size) {
    const float* xh = (const float*)d_in[0];   // x_hat
    const float* x  = (const float*)d_in[1];   // x

    void *p1 = nullptr, *p2 = nullptr;
    cudaGetSymbolAddress(&p1, g_s1);
    cudaGetSymbolAddress(&p2, g_s2);
    cudaMemsetAsync(p1, 0, TOTF * sizeof(double));
    cudaMemsetAsync(p2, 0, TOTF * sizeof(double));

    stft_kernel<  32,    0><<<740, 256>>>(x, xh);
    stft_kernel<  64,   17><<<740, 256>>>(x, xh);
    stft_kernel< 128,   50><<<740, 256>>>(x, xh);
    stft_kernel< 256,  115><<<740, 256>>>(x, xh);
    stft_kernel< 512,  244><<<740, 256>>>(x, xh);
    stft_kernel<1024,  501><<<740, 256>>>(x, xh);
    stft_kernel<2048, 1014><<<740, 256>>>(x, xh);

    loss_kernel<<<1, 512>>>((float*)d_out);
}

// round 7
// speedup vs baseline: 1.4184x; 1.0610x over previous
#include <cuda_runtime.h>
#include <math.h>

#define BATCH 16
#define NSAMP 72000
#define TOTF  2039   // 17+33+65+129+257+513+1025

__device__ double g_s1[TOTF];
__device__ double g_s2[TOTF];

__host__ __device__ constexpr int ilog2c(int n) { return (n <= 1) ? 0 : 1 + ilog2c(n >> 1); }

// Blocks runtime constant folding while preserving exact double bits.
__device__ __forceinline__ double opaque_d(double x) { volatile double t = x; return t; }

__device__ __forceinline__ float2 cadd(float2 a, float2 b) { return make_float2(a.x + b.x, a.y + b.y); }
__device__ __forceinline__ float2 csub(float2 a, float2 b) { return make_float2(a.x - b.x, a.y - b.y); }
__device__ __forceinline__ float2 cmul(float2 a, float2 b) {
    return make_float2(a.x * b.x - a.y * b.y, a.x * b.y + a.y * b.x);
}

#define BLKS_PER_SCALE 740
// Dynamic smem layout (shared by all scales): buf 2048 float2, then tw/win/red.
#define SMEM_DYN (16384 + 8 * 2048 + 8 * 1032)

// Packed complex FFT (z = x + i*x_hat) over all frames of one scale.
// Radix-4 fused stages; first two stages fused into the windowed load;
// leftover radix-2 for odd log2(N). XOR bank swizzle on buf.
// TPF = NFFT/8 -> BPT4=2 (ILP); frame-scoped synchronization.
// Twiddle trick: w_L^j = (w_{2L}^j)^2 -> one LDS per butterfly instead of two.
template<int NFFT, int OFF>
__device__ __forceinline__ void stft_body(const float* __restrict__ x,
                                          const float* __restrict__ xh,
                                          int blk, char* raw) {
    constexpr int HOP   = NFFT / 4;
    constexpr int PAD   = NFFT / 2;
    constexpr int T     = 1 + NSAMP / HOP;
    constexpr int TOTAL = BATCH * T;
    constexpr int F     = NFFT / 2 + 1;
    constexpr int LOG2N = ilog2c(NFFT);
    constexpr int TPB   = 256;
    constexpr int Q     = NFFT / 4;
    constexpr int TPF   = (NFFT / 8 > TPB) ? TPB : (NFFT / 8);  // threads per frame
    constexpr int FPB   = TPB / TPF;                   // frames per block
    constexpr int BPT4  = Q / TPF;                     // fused butterflies/thread (2)
    constexpr int KPT   = (F + TPF - 1) / TPF;         // freq bins per thread (unpack)
    constexpr int BUFSZ = FPB * NFFT;                  // == 2048 for all scales
    static_assert(BUFSZ == 2048, "layout assumes BUFSZ==2048");
    constexpr int S     = ilog2c(BUFSZ) - 4;

    float2* buf  = (float2*)raw;
    float2* tw   = (float2*)(raw + 16384);
    float*  win  = (float*)(raw + 16384 + 4 * NFFT);
    float*  red1 = (float*)(raw + 16384 + 8 * NFFT);
    float*  red2 = (float*)(raw + 16384 + 8 * NFFT + 4 * F);

    const int tid  = threadIdx.x;
    const int slot = tid / TPF;
    const int ltid = tid % TPF;

    // Bank swizzle: bijective (modifies only bits 0-3 by a function of bits>=4).
    auto sw = [](int i) { return i ^ (((i >> S) ^ (i >> 4)) & 15); };

    // Frame-scoped sync.
    auto fsync = [&]() {
        if constexpr (TPF <= 32) { __syncwarp(); }
        else if constexpr (TPF >= TPB) { __syncthreads(); }
        else { asm volatile("bar.sync %0, %1;" :: "r"(slot + 1), "r"(TPF) : "memory"); }
    };

    // Twiddles: tw[t] = exp(-2*pi*i*t/N). Window: periodic hann / sqrt(0.375*N).
    const float rnorm = rsqrtf(0.375f * (float)NFFT);
    for (int t = tid; t < NFFT / 2; t += TPB) {
        float s, c;
        sincospif(2.0f * (float)t / (float)NFFT, &s, &c);
        tw[t] = make_float2(c, -s);
    }
    for (int t = tid; t < NFFT; t += TPB) {
        win[t] = (0.5f - 0.5f * cospif(2.0f * (float)t / (float)NFFT)) * rnorm;
    }
    for (int t = tid; t < F; t += TPB) { red1[t] = 0.0f; red2[t] = 0.0f; }

    float acc1[KPT], acc2[KPT];
#pragma unroll
    for (int r = 0; r < KPT; r++) { acc1[r] = 0.0f; acc2[r] = 0.0f; }

    __syncthreads();

    for (int base = blk * FPB; base < TOTAL; base += BLKS_PER_SCALE * FPB) {
        const int gf = base + slot;
        const bool valid = (gf < TOTAL);

        // Load + window + first fused radix-4 stage (stages len=2,4; twiddles = 1).
        if (valid) {
            const int b  = gf / T;
            const int t0 = gf - b * T;
            const int start = t0 * HOP - PAD;
            const float* xb  = x  + b * NSAMP;
            const float* xhb = xh + b * NSAMP;
#pragma unroll
            for (int r = 0; r < BPT4; r++) {
                const int idx = ltid + r * TPF;                       // [0, N/4)
                const int g   = (int)(__brev((unsigned)idx) >> (32 - (LOG2N - 2)));
                float2 a[4];
                constexpr int offs4[4] = {0, NFFT / 2, NFFT / 4, 3 * NFFT / 4};
#pragma unroll
                for (int k = 0; k < 4; k++) {
                    const int tt = idx + offs4[k];
                    int s = start + tt;
                    s = (s < 0) ? -s : s;                        // reflect left
                    s = (s >= NSAMP) ? (2 * NSAMP - 2 - s) : s;  // reflect right
                    const float wv = win[tt];
                    a[k] = make_float2(xb[s] * wv, xhb[s] * wv);
                }
                const float2 c0 = cadd(a[0], a[1]), c1 = csub(a[0], a[1]);
                const float2 c2 = cadd(a[2], a[3]), c3 = csub(a[2], a[3]);
                const int wb = slot * NFFT + 4 * g;
                buf[sw(wb + 0)] = cadd(c0, c2);
                buf[sw(wb + 2)] = csub(c0, c2);
                buf[sw(wb + 1)] = make_float2(c1.x + c3.y, c1.y - c3.x);  // c1 - i*c3
                buf[sw(wb + 3)] = make_float2(c1.x - c3.y, c1.y + c3.x);  // c1 + i*c3
            }
        }
        fsync();

        // Fused radix-4 stages: pair (len=L, len=2L) for L = 8, 32, 128, 512...
        // t2 = w_{2L}^j from LDS; t1 = w_L^j = t2^2 (exact identity, saves an LDS).
#pragma unroll
        for (int L = 8; 2 * L <= NFFT; L *= 4) {
#pragma unroll
            for (int r = 0; r < BPT4; r++) {
                const int idx = ltid + r * TPF;              // [0, N/4)
                const int j   = idx & (L / 2 - 1);
                const int g   = idx / (L / 2);
                const int p   = slot * NFFT + g * (2 * L) + j;
                float2 a0 = buf[sw(p)];
                float2 a1 = buf[sw(p + L / 2)];
                float2 a2 = buf[sw(p + L)];
                float2 a3 = buf[sw(p + 3 * L / 2)];
                const float2 t2 = tw[j * (NFFT / (2 * L))];  // w_{2L}^j
                const float2 t1 = cmul(t2, t2);              // w_L^j
                const float2 u1 = cmul(t1, a1), u3 = cmul(t1, a3);
                const float2 c0 = cadd(a0, u1), c1 = csub(a0, u1);
                const float2 c2 = cadd(a2, u3), c3 = csub(a2, u3);
                const float2 v2 = cmul(t2, c2), v3 = cmul(t2, c3);
                buf[sw(p)]             = cadd(c0, v2);
                buf[sw(p + L)]         = csub(c0, v2);
                buf[sw(p + L / 2)]     = make_float2(c1.x + v3.y, c1.y - v3.x);  // c1 - i*v3
                buf[sw(p + 3 * L / 2)] = make_float2(c1.x - v3.y, c1.y + v3.x);  // c1 + i*v3
            }
            fsync();
        }

        // Leftover radix-2 stage (len = N) for odd log2(N).
        if constexpr (LOG2N & 1) {
#pragma unroll
            for (int r = 0; r < 2 * BPT4; r++) {
                const int idx = ltid + r * TPF;              // [0, N/2)
                const int p = slot * NFFT + idx;
                const float2 a  = buf[sw(p)];
                const float2 b2 = buf[sw(p + NFFT / 2)];
                const float2 t  = cmul(tw[idx], b2);
                buf[sw(p)]            = cadd(a, t);
                buf[sw(p + NFFT / 2)] = csub(a, t);
            }
            fsync();
        }

        // Unpack X (from x) and Xh (from x_hat), accumulate stats
        if (valid) {
#pragma unroll
            for (int r = 0; r < KPT; r++) {
                const int k = ltid + r * TPF;
                if (k <= NFFT / 2) {
                    const float2 zk = buf[sw(slot * NFFT + k)];
                    const float2 zn = buf[sw(slot * NFFT + ((NFFT - k) & (NFFT - 1)))];
                    const float ar = 0.5f * (zk.x + zn.x);
                    const float ai = 0.5f * (zk.y - zn.y);
                    const float br = 0.5f * (zk.y + zn.y);
                    const float bi = 0.5f * (zn.x - zk.x);
                    const float magA = sqrtf(ar * ar + ai * ai);
                    const float magB = sqrtf(br * br + bi * bi);
                    const float d = magB - magA;          // |Xh| - |X|
                    acc1[r] += fabsf(d);
                    acc2[r] += d * d;
                }
            }
        }
        fsync();   // protect buf before next load (frame-scoped)
    }

    // Block reduce: registers -> shared float
#pragma unroll
    for (int r = 0; r < KPT; r++) {
        const int k = ltid + r * TPF;
        if (k <= NFFT / 2) {
            atomicAdd(&red1[k], acc1[r]);
            atomicAdd(&red2[k], acc2[r]);
        }
    }
    __syncthreads();

    for (int k = tid; k < F; k += TPB) {
        atomicAdd(&g_s1[OFF + k], (double)red1[k]);
        atomicAdd(&g_s2[OFF + k], (double)red2[k]);
    }
}

// All 7 scales in one launch: block range -> scale (uniform per block, so
// block barriers remain legal). One tail instead of seven + no launch gaps.
__global__ void __launch_bounds__(256)
fused_stft(const float* __restrict__ x, const float* __restrict__ xh) {
    extern __shared__ char raw[];
    const int b = blockIdx.x;
    if      (b < 1 * BLKS_PER_SCALE) stft_body<  32,    0>(x, xh, b - 0 * BLKS_PER_SCALE, raw);
    else if (b < 2 * BLKS_PER_SCALE) stft_body<  64,   17>(x, xh, b - 1 * BLKS_PER_SCALE, raw);
    else if (b < 3 * BLKS_PER_SCALE) stft_body< 128,   50>(x, xh, b - 2 * BLKS_PER_SCALE, raw);
    else if (b < 4 * BLKS_PER_SCALE) stft_body< 256,  115>(x, xh, b - 3 * BLKS_PER_SCALE, raw);
    else if (b < 5 * BLKS_PER_SCALE) stft_body< 512,  244>(x, xh, b - 4 * BLKS_PER_SCALE, raw);
    else if (b < 6 * BLKS_PER_SCALE) stft_body<1024,  501>(x, xh, b - 5 * BLKS_PER_SCALE, raw);
    else                             stft_body<2048, 1014>(x, xh, b - 6 * BLKS_PER_SCALE, raw);
}

// Mel-band combine. One thread per (scale, band-candidate). Band m support =
// bins f with f_pts[m] < f*step < f_pts[m+2] (strict). All interior decisions
// have >=1e-3 relative margins (safe in double). The ONLY knife-edge is the
// Nyquist bin (freq == 12000.0 exactly) vs f_pts[65] (a log10/pow round-trip
// of 12000, = 12000 +- few ulp, libm-rounding dependent). We reproduce the
// libdevice decision and take the OPPOSITE (matches numpy; verified rel_err=0).
__global__ void loss_kernel(float* out) {
    __shared__ int    nb[7];
    __shared__ double sl[7];
    const int tid = threadIdx.x;
    if (tid < 7) { nb[tid] = 0; sl[tid] = 0.0; }
    __syncthreads();

    const int scale = tid >> 6;
    const int m     = tid & 63;

    if (scale < 7) {
        const int offs[7] = {0, 17, 50, 115, 244, 501, 1014};
        const int Ts[7]   = {9001, 4501, 2251, 1126, 563, 282, 141};
        const int nfft = 32 << scale;
        const int F = nfft / 2 + 1;
        const double step = 12000.0 / (double)(F - 1);
        const double melmax = 2595.0 * log10(1.0 + 12000.0 / 700.0);

        const double e65  = (melmax * 65.0 / 65.0) / 2595.0;
        const double hi65 = 700.0 * (pow(10.0, opaque_d(e65)) - 1.0);
        const bool   nyq_in = !(hi65 > 12000.0);

        int a[2], b[2];   // [0] = band m, [1] = band m-1
        for (int q = 0; q < 2; q++) {
            const int mm = m - q;
            if (mm < 0) { a[q] = 0; b[q] = 0; continue; }
            const double lo = 700.0 * (pow(10.0, opaque_d(melmax * (double)mm / 65.0) / 2595.0) - 1.0);
            int a0 = (int)floor(lo / step); if ((double)a0 * step <= lo) a0++;  // first f: f*step > lo
            if (a0 < 0) a0 = 0;
            int b0;
            if (mm + 2 == 65) {
                b0 = nyq_in ? F : (F - 1);
            } else {
                const double hi = 700.0 * (pow(10.0, opaque_d(melmax * (double)(mm + 2) / 65.0) / 2595.0) - 1.0);
                b0 = (int)floor(hi / step); if ((double)b0 * step <  hi) b0++;  // last f+1: f*step < hi
                if (b0 > F) b0 = F;
            }
            a[q] = a0; b[q] = b0;
        }
        const bool nonempty = (b[0] > a[0]);
        const bool dup = (m > 0) && (a[0] == a[1]) && (b[0] == b[1]) && nonempty;
        if (nonempty && !dup) {
            atomicAdd(&nb[scale], 1);
            double s1 = 0.0, s2 = 0.0;
            for (int f = a[0]; f < b[0]; f++) {
                s1 += g_s1[offs[scale] + f];
                s2 += g_s2[offs[scale] + f];
            }
            const double cnt = (double)(b[0] - a[0]) * (double)BATCH * (double)Ts[scale];
            const double val = s1 / cnt + sqrt(s2 / cnt + 1e-8);
            atomicAdd(&sl[scale], val);
        }
    }
    __syncthreads();

    if (tid == 0) {
        double tot = 0.0;
        for (int s = 0; s < 7; s++) tot += sl[s] / (double)nb[s];
        out[0] = (float)(tot / 7.0);
    }
}

extern "C" void kernel_launch(void* const* d_in, const int* in_sizes, int n_in,
                              void* d_out, int out_size) {
    const float* xh = (const float*)d_in[0];   // x_hat
    const float* x  = (const float*)d_in[1];   // x

    void *p1 = nullptr, *p2 = nullptr;
    cudaGetSymbolAddress(&p1, g_s1);
    cudaGetSymbolAddress(&p2, g_s2);
    cudaMemsetAsync(p1, 0, TOTF * sizeof(double));
    cudaMemsetAsync(p2, 0, TOTF * sizeof(double));

    fused_stft<<<7 * BLKS_PER_SCALE, 256, SMEM_DYN>>>(x, xh);

    loss_kernel<<<1, 512>>>((float*)d_out);
}

// round 8
// speedup vs baseline: 1.6749x; 1.1809x over previous
#include <cuda_runtime.h>
#include <math.h>

#define BATCH 16
#define NSAMP 72000
#define TOTF  2039   // 17+33+65+129+257+513+1025

__device__ double g_s1[TOTF];
__device__ double g_s2[TOTF];
__device__ float2 g_tw[2032];    // per-scale twiddles, packed
__device__ float  g_win[4064];   // per-scale windows, packed
__device__ int2   g_ab[7 * 64];  // band slices (a,b) per (scale, candidate)
__device__ int    g_nb[7];
__device__ double g_acc;
__device__ int    g_done;

__host__ __device__ constexpr int ilog2c(int n) { return (n <= 1) ? 0 : 1 + ilog2c(n >> 1); }

// Blocks runtime constant folding while preserving exact double bits.
__device__ __forceinline__ double opaque_d(double x) { volatile double t = x; return t; }

__device__ __forceinline__ float2 cadd(float2 a, float2 b) { return make_float2(a.x + b.x, a.y + b.y); }
__device__ __forceinline__ float2 csub(float2 a, float2 b) { return make_float2(a.x - b.x, a.y - b.y); }
__device__ __forceinline__ float2 cmul(float2 a, float2 b) {
    return make_float2(a.x * b.x - a.y * b.y, a.x * b.y + a.y * b.x);
}

#define BLKS_PER_SCALE 740
#define SMEM_DYN (16384 + 8 * 2048 + 8 * 1032)

__device__ __constant__ int c_twoff[7]  = {0, 16, 48, 112, 240, 496, 1008};
__device__ __constant__ int c_winoff[7] = {0, 32, 96, 224, 480, 992, 2016};
__device__ __constant__ int c_soff[7]   = {0, 17, 50, 115, 244, 501, 1014};
__device__ __constant__ int c_T[7]      = {9001, 4501, 2251, 1126, 563, 282, 141};

// ---------------------------------------------------------------------------
// Init: zero accumulators, precompute twiddles/windows, compute mel band
// edges (bit-identical decision logic to the verified rel_err=0 version:
// strict f_pts[m] < f*step < f_pts[m+2], Nyquist decided by flipped libdevice
// pow round-trip). Runs once before the STFT kernel; no dependencies.
// ---------------------------------------------------------------------------
__global__ void __launch_bounds__(256) init_kernel() {
    const int s   = blockIdx.x;   // 0..6
    const int tid = threadIdx.x;
    const int NFFT = 32 << s;

    for (int i = s * 256 + tid; i < TOTF; i += 7 * 256) { g_s1[i] = 0.0; g_s2[i] = 0.0; }
    if (s == 0 && tid == 0) { g_acc = 0.0; g_done = 0; }

    const float rnorm = rsqrtf(0.375f * (float)NFFT);
    for (int t = tid; t < NFFT / 2; t += 256) {
        float sn, cs;
        sincospif(2.0f * (float)t / (float)NFFT, &sn, &cs);
        g_tw[c_twoff[s] + t] = make_float2(cs, -sn);
    }
    for (int t = tid; t < NFFT; t += 256) {
        g_win[c_winoff[s] + t] = (0.5f - 0.5f * cospif(2.0f * (float)t / (float)NFFT)) * rnorm;
    }

    if (tid < 64) {
        const int m = tid;
        const int F = NFFT / 2 + 1;
        const double step = 12000.0 / (double)(F - 1);
        const double melmax = 2595.0 * log10(1.0 + 12000.0 / 700.0);

        const double e65  = (melmax * 65.0 / 65.0) / 2595.0;
        const double hi65 = 700.0 * (pow(10.0, opaque_d(e65)) - 1.0);
        const bool   nyq_in = !(hi65 > 12000.0);

        int a[2], b[2];   // [0] = band m, [1] = band m-1
        for (int q = 0; q < 2; q++) {
            const int mm = m - q;
            if (mm < 0) { a[q] = 0; b[q] = 0; continue; }
            const double lo = 700.0 * (pow(10.0, opaque_d(melmax * (double)mm / 65.0) / 2595.0) - 1.0);
            int a0 = (int)floor(lo / step); if ((double)a0 * step <= lo) a0++;  // first f: f*step > lo
            if (a0 < 0) a0 = 0;
            int b0;
            if (mm + 2 == 65) {
                b0 = nyq_in ? F : (F - 1);
            } else {
                const double hi = 700.0 * (pow(10.0, opaque_d(melmax * (double)(mm + 2) / 65.0) / 2595.0) - 1.0);
                b0 = (int)floor(hi / step); if ((double)b0 * step <  hi) b0++;  // last f+1: f*step < hi
                if (b0 > F) b0 = F;
            }
            a[q] = a0; b[q] = b0;
        }
        const bool nonempty = (b[0] > a[0]);
        const bool dup = (m > 0) && (a[0] == a[1]) && (b[0] == b[1]) && nonempty;
        const bool keep = nonempty && !dup;
        g_ab[s * 64 + m] = keep ? make_int2(a[0], b[0]) : make_int2(0, 0);
        const unsigned mask = __ballot_sync(0xffffffffu, keep && tid < 64);
        if ((tid & 31) == 0) {
            if (tid == 0) g_nb[s] = 0;
        }
    }
    __syncthreads();
    if (tid == 0) {
        int cnt = 0;
        for (int m = 0; m < 64; m++) { int2 ab = g_ab[s * 64 + m]; if (ab.y > ab.x) cnt++; }
        g_nb[s] = cnt;
    }
}

// ---------------------------------------------------------------------------
// Packed complex FFT (z = x + i*x_hat) over all frames of one scale.
// Radix-4 fused stages; first two stages fused into the windowed load;
// leftover radix-2 for odd log2(N). XOR bank swizzle on buf.
// TPF = NFFT/8 -> BPT4=2 (ILP); frame-scoped synchronization.
// tw/win copied from precomputed global (no per-block sincospif).
// ---------------------------------------------------------------------------
template<int NFFT, int OFF, int SCALE>
__device__ __forceinline__ void stft_body(const float* __restrict__ x,
                                          const float* __restrict__ xh,
                                          int blk, char* raw) {
    constexpr int HOP   = NFFT / 4;
    constexpr int PAD   = NFFT / 2;
    constexpr int T     = 1 + NSAMP / HOP;
    constexpr int TOTAL = BATCH * T;
    constexpr int F     = NFFT / 2 + 1;
    constexpr int LOG2N = ilog2c(NFFT);
    constexpr int TPB   = 256;
    constexpr int Q     = NFFT / 4;
    constexpr int TPF   = (NFFT / 8 > TPB) ? TPB : (NFFT / 8);  // threads per frame
    constexpr int FPB   = TPB / TPF;                   // frames per block
    constexpr int BPT4  = Q / TPF;                     // fused butterflies/thread (2)
    constexpr int KPT   = (F + TPF - 1) / TPF;         // freq bins per thread (unpack)
    constexpr int BUFSZ = FPB * NFFT;                  // == 2048 for all scales
    static_assert(BUFSZ == 2048, "layout assumes BUFSZ==2048");
    constexpr int S     = ilog2c(BUFSZ) - 4;

    float2* buf  = (float2*)raw;
    float2* tw   = (float2*)(raw + 16384);
    float*  win  = (float*)(raw + 16384 + 4 * NFFT);
    float*  red1 = (float*)(raw + 16384 + 8 * NFFT);
    float*  red2 = (float*)(raw + 16384 + 8 * NFFT + 4 * F);

    const int tid  = threadIdx.x;
    const int slot = tid / TPF;
    const int ltid = tid % TPF;

    // Bank swizzle: bijective (modifies only bits 0-3 by a function of bits>=4).
    auto sw = [](int i) { return i ^ (((i >> S) ^ (i >> 4)) & 15); };

    // Frame-scoped sync.
    auto fsync = [&]() {
        if constexpr (TPF <= 32) { __syncwarp(); }
        else if constexpr (TPF >= TPB) { __syncthreads(); }
        else { asm volatile("bar.sync %0, %1;" :: "r"(slot + 1), "r"(TPF) : "memory"); }
    };

    // Copy precomputed twiddles/window (L2-hot after init kernel).
    for (int t = tid; t < NFFT / 2; t += TPB) tw[t]  = g_tw[c_twoff[SCALE] + t];
    for (int t = tid; t < NFFT; t += TPB)     win[t] = g_win[c_winoff[SCALE] + t];
    for (int t = tid; t < F; t += TPB) { red1[t] = 0.0f; red2[t] = 0.0f; }

    float acc1[KPT], acc2[KPT];
#pragma unroll
    for (int r = 0; r < KPT; r++) { acc1[r] = 0.0f; acc2[r] = 0.0f; }

    __syncthreads();

    for (int base = blk * FPB; base < TOTAL; base += BLKS_PER_SCALE * FPB) {
        const int gf = base + slot;
        const bool valid = (gf < TOTAL);

        // Load + window + first fused radix-4 stage (stages len=2,4; twiddles = 1).
        if (valid) {
            const int b  = gf / T;
            const int t0 = gf - b * T;
            const int start = t0 * HOP - PAD;
            const float* xb  = x  + b * NSAMP;
            const float* xhb = xh + b * NSAMP;
#pragma unroll
            for (int r = 0; r < BPT4; r++) {
                const int idx = ltid + r * TPF;                       // [0, N/4)
                const int g   = (int)(__brev((unsigned)idx) >> (32 - (LOG2N - 2)));
                float2 a[4];
                constexpr int offs4[4] = {0, NFFT / 2, NFFT / 4, 3 * NFFT / 4};
#pragma unroll
                for (int k = 0; k < 4; k++) {
                    const int tt = idx + offs4[k];
                    int s = start + tt;
                    s = (s < 0) ? -s : s;                        // reflect left
                    s = (s >= NSAMP) ? (2 * NSAMP - 2 - s) : s;  // reflect right
                    const float wv = win[tt];
                    a[k] = make_float2(xb[s] * wv, xhb[s] * wv);
                }
                const float2 c0 = cadd(a[0], a[1]), c1 = csub(a[0], a[1]);
                const float2 c2 = cadd(a[2], a[3]), c3 = csub(a[2], a[3]);
                const int wb = slot * NFFT + 4 * g;
                buf[sw(wb + 0)] = cadd(c0, c2);
                buf[sw(wb + 2)] = csub(c0, c2);
                buf[sw(wb + 1)] = make_float2(c1.x + c3.y, c1.y - c3.x);  // c1 - i*c3
                buf[sw(wb + 3)] = make_float2(c1.x - c3.y, c1.y + c3.x);  // c1 + i*c3
            }
        }
        fsync();

        // Fused radix-4 stages: pair (len=L, len=2L) for L = 8, 32, 128, 512...
        // t2 = w_{2L}^j from LDS; t1 = w_L^j = t2^2 (exact identity, saves an LDS).
#pragma unroll
        for (int L = 8; 2 * L <= NFFT; L *= 4) {
#pragma unroll
            for (int r = 0; r < BPT4; r++) {
                const int idx = ltid + r * TPF;              // [0, N/4)
                const int j   = idx & (L / 2 - 1);
                const int g   = idx / (L / 2);
                const int p   = slot * NFFT + g * (2 * L) + j;
                float2 a0 = buf[sw(p)];
                float2 a1 = buf[sw(p + L / 2)];
                float2 a2 = buf[sw(p + L)];
                float2 a3 = buf[sw(p + 3 * L / 2)];
                const float2 t2 = tw[j * (NFFT / (2 * L))];  // w_{2L}^j
                const float2 t1 = cmul(t2, t2);              // w_L^j
                const float2 u1 = cmul(t1, a1), u3 = cmul(t1, a3);
                const float2 c0 = cadd(a0, u1), c1 = csub(a0, u1);
                const float2 c2 = cadd(a2, u3), c3 = csub(a2, u3);
                const float2 v2 = cmul(t2, c2), v3 = cmul(t2, c3);
                buf[sw(p)]             = cadd(c0, v2);
                buf[sw(p + L)]         = csub(c0, v2);
                buf[sw(p + L / 2)]     = make_float2(c1.x + v3.y, c1.y - v3.x);  // c1 - i*v3
                buf[sw(p + 3 * L / 2)] = make_float2(c1.x - v3.y, c1.y + v3.x);  // c1 + i*v3
            }
            fsync();
        }

        // Leftover radix-2 stage (len = N) for odd log2(N).
        if constexpr (LOG2N & 1) {
#pragma unroll
            for (int r = 0; r < 2 * BPT4; r++) {
                const int idx = ltid + r * TPF;              // [0, N/2)
                const int p = slot * NFFT + idx;
                const float2 a  = buf[sw(p)];
                const float2 b2 = buf[sw(p + NFFT / 2)];
                const float2 t  = cmul(tw[idx], b2);
                buf[sw(p)]            = cadd(a, t);
                buf[sw(p + NFFT / 2)] = csub(a, t);
            }
            fsync();
        }

        // Unpack X (from x) and Xh (from x_hat), accumulate stats
        if (valid) {
#pragma unroll
            for (int r = 0; r < KPT; r++) {
                const int k = ltid + r * TPF;
                if (k <= NFFT / 2) {
                    const float2 zk = buf[sw(slot * NFFT + k)];
                    const float2 zn = buf[sw(slot * NFFT + ((NFFT - k) & (NFFT - 1)))];
                    const float ar = 0.5f * (zk.x + zn.x);
                    const float ai = 0.5f * (zk.y - zn.y);
                    const float br = 0.5f * (zk.y + zn.y);
                    const float bi = 0.5f * (zn.x - zk.x);
                    const float magA = sqrtf(ar * ar + ai * ai);
                    const float magB = sqrtf(br * br + bi * bi);
                    const float d = magB - magA;          // |Xh| - |X|
                    acc1[r] += fabsf(d);
                    acc2[r] += d * d;
                }
            }
        }
        fsync();   // protect buf before next load (frame-scoped)
    }

    // Block reduce: registers -> shared float
#pragma unroll
    for (int r = 0; r < KPT; r++) {
        const int k = ltid + r * TPF;
        if (k <= NFFT / 2) {
            atomicAdd(&red1[k], acc1[r]);
            atomicAdd(&red2[k], acc2[r]);
        }
    }
    __syncthreads();

    for (int k = tid; k < F; k += TPB) {
        atomicAdd(&g_s1[OFF + k], (double)red1[k]);
        atomicAdd(&g_s2[OFF + k], (double)red2[k]);
    }
}

// All 7 scales in one launch; min 4 blocks/SM (forces <=64 regs, occ ~50%).
__global__ void __launch_bounds__(256, 4)
fused_stft(const float* __restrict__ x, const float* __restrict__ xh) {
    extern __shared__ char raw[];
    const int b = blockIdx.x;
    if      (b < 1 * BLKS_PER_SCALE) stft_body<  32,    0, 0>(x, xh, b - 0 * BLKS_PER_SCALE, raw);
    else if (b < 2 * BLKS_PER_SCALE) stft_body<  64,   17, 1>(x, xh, b - 1 * BLKS_PER_SCALE, raw);
    else if (b < 3 * BLKS_PER_SCALE) stft_body< 128,   50, 2>(x, xh, b - 2 * BLKS_PER_SCALE, raw);
    else if (b < 4 * BLKS_PER_SCALE) stft_body< 256,  115, 3>(x, xh, b - 3 * BLKS_PER_SCALE, raw);
    else if (b < 5 * BLKS_PER_SCALE) stft_body< 512,  244, 4>(x, xh, b - 4 * BLKS_PER_SCALE, raw);
    else if (b < 6 * BLKS_PER_SCALE) stft_body<1024,  501, 5>(x, xh, b - 5 * BLKS_PER_SCALE, raw);
    else                             stft_body<2048, 1014, 6>(x, xh, b - 6 * BLKS_PER_SCALE, raw);
}

// ---------------------------------------------------------------------------
// Loss: 7 blocks (one per scale). One warp per band candidate (strided);
// lane-parallel slice sums + shuffle reduce kill the serial DADD chain.
// Last-finisher block writes the final float.
// ---------------------------------------------------------------------------
__global__ void __launch_bounds__(256) loss_kernel(float* out) {
    const int s    = blockIdx.x;
    const int tid  = threadIdx.x;
    const int w    = tid >> 5;
    const int lane = tid & 31;

    __shared__ double ssum;
    if (tid == 0) ssum = 0.0;
    __syncthreads();

    for (int cand = w; cand < 64; cand += 8) {
        const int2 ab = g_ab[s * 64 + cand];
        if (ab.y > ab.x) {
            double p1 = 0.0, p2 = 0.0;
            for (int f = ab.x + lane; f < ab.y; f += 32) {
                p1 += g_s1[c_soff[s] + f];
                p2 += g_s2[c_soff[s] + f];
            }
#pragma unroll
            for (int o = 16; o > 0; o >>= 1) {
                p1 += __shfl_down_sync(0xffffffffu, p1, o);
                p2 += __shfl_down_sync(0xffffffffu, p2, o);
            }
            if (lane == 0) {
                const double cnt = (double)(ab.y - ab.x) * (double)BATCH * (double)c_T[s];
                const double val = p1 / cnt + sqrt(p2 / cnt + 1e-8);
                atomicAdd(&ssum, val);
            }
        }
    }
    __syncthreads();

    if (tid == 0) {
        const double contrib = ssum / (double)g_nb[s] / 7.0;
        atomicAdd(&g_acc, contrib);
        __threadfence();
        const int old = atomicAdd(&g_done, 1);
        if (old == 6) {
            out[0] = (float)(*(volatile double*)&g_acc);
        }
    }
}

extern "C" void kernel_launch(void* const* d_in, const int* in_sizes, int n_in,
                              void* d_out, int out_size) {
    const float* xh = (const float*)d_in[0];   // x_hat
    const float* x  = (const float*)d_in[1];   // x

    init_kernel<<<7, 256>>>();
    fused_stft<<<7 * BLKS_PER_SCALE, 256, SMEM_DYN>>>(x, xh);
    loss_kernel<<<7, 256>>>((float*)d_out);
}

// round 9
// speedup vs baseline: 2.2476x; 1.3419x over previous
#include <cuda_runtime.h>
#include <math.h>

#define BATCH 16
#define NSAMP 72000
#define TOTF  2039   // 17+33+65+129+257+513+1025

__device__ double g_s1[TOTF];
__device__ double g_s2[TOTF];
__device__ int2   g_ab[7 * 64];  // band slices (a,b) per (scale, candidate)
__device__ int    g_nb[7];
__device__ double g_acc;
__device__ int    g_done;

__host__ __device__ constexpr int ilog2c(int n) { return (n <= 1) ? 0 : 1 + ilog2c(n >> 1); }

// Blocks runtime constant folding while preserving exact double bits.
__device__ __forceinline__ double opaque_d(double x) { volatile double t = x; return t; }

__device__ __forceinline__ float2 cadd(float2 a, float2 b) { return make_float2(a.x + b.x, a.y + b.y); }
__device__ __forceinline__ float2 csub(float2 a, float2 b) { return make_float2(a.x - b.x, a.y - b.y); }
__device__ __forceinline__ float2 cmul(float2 a, float2 b) {
    return make_float2(a.x * b.x - a.y * b.y, a.x * b.y + a.y * b.x);
}

#define BLKS_PER_SCALE 740
#define SMEM_DYN (16384 + 8 * 2048 + 8 * 1032)
#define RQ 0.70710678118654752440f

__device__ __constant__ int c_soff[7] = {0, 17, 50, 115, 244, 501, 1014};
__device__ __constant__ int c_T[7]    = {9001, 4501, 2251, 1126, 563, 282, 141};

template<int S>
__device__ __forceinline__ int swz(int i) { return i ^ (((i >> S) ^ (i >> 4)) & 15); }

// Radix-4 SMEM pass: stages (L, 2L). t2 = w_{2L}^j from LDS, w_L^j = t2^2.
template<int NFFT, int L, int TPF, int S>
__device__ __forceinline__ void radix4_pass(float2* buf, const float2* tw, int base, int ltid) {
    constexpr int BPT = (NFFT / 4) / TPF;
#pragma unroll
    for (int r = 0; r < BPT; r++) {
        const int idx = ltid + r * TPF;
        const int j   = idx & (L / 2 - 1);
        const int g   = idx / (L / 2);
        const int p   = base + g * (2 * L) + j;
        float2 a0 = buf[swz<S>(p)];
        float2 a1 = buf[swz<S>(p + L / 2)];
        float2 a2 = buf[swz<S>(p + L)];
        float2 a3 = buf[swz<S>(p + 3 * L / 2)];
        const float2 t2 = tw[j * (NFFT / (2 * L))];  // w_{2L}^j
        const float2 t1 = cmul(t2, t2);              // w_L^j
        const float2 u1 = cmul(t1, a1), u3 = cmul(t1, a3);
        const float2 c0 = cadd(a0, u1), c1 = csub(a0, u1);
        const float2 c2 = cadd(a2, u3), c3 = csub(a2, u3);
        const float2 v2 = cmul(t2, c2), v3 = cmul(t2, c3);
        buf[swz<S>(p)]             = cadd(c0, v2);
        buf[swz<S>(p + L)]         = csub(c0, v2);
        buf[swz<S>(p + L / 2)]     = make_float2(c1.x + v3.y, c1.y - v3.x);  // c1 - i*v3
        buf[swz<S>(p + 3 * L / 2)] = make_float2(c1.x - v3.y, c1.y + v3.x);  // c1 + i*v3
    }
}

// Radix-8 SMEM pass: stages (L, 2L, 4L) in one round trip.
// t4 = w_{4L}^j (one LDS); t2 = t4^2, t1 = t4^4 (exact identities).
// Stage-2 odd-slot twiddle = -i*t2; stage-3 factors = t4 * w8^m.
template<int NFFT, int L, int TPF, int S>
__device__ __forceinline__ void radix8_pass(float2* buf, const float2* tw, int base, int ltid) {
    constexpr int BPT = (NFFT / 8) / TPF;
#pragma unroll
    for (int r = 0; r < BPT; r++) {
        const int idx = ltid + r * TPF;
        const int j   = idx & (L / 2 - 1);
        const int g   = idx / (L / 2);
        const int p   = base + g * (4 * L) + j;
        float2 b[8];
#pragma unroll
        for (int m = 0; m < 8; m++) b[m] = buf[swz<S>(p + m * (L / 2))];
        const float2 t4 = tw[j * (NFFT / (4 * L))];  // w_{4L}^j
        const float2 t2 = cmul(t4, t4);              // w_{2L}^j
        const float2 t1 = cmul(t2, t2);              // w_L^j
        // stage 1 (len L): pairs (0,1),(2,3),(4,5),(6,7), twiddle t1
        float2 c[8];
#pragma unroll
        for (int m = 0; m < 4; m++) {
            const float2 u = cmul(t1, b[2 * m + 1]);
            c[2 * m]     = cadd(b[2 * m], u);
            c[2 * m + 1] = csub(b[2 * m], u);
        }
        // stage 2 (len 2L): pairs (0,2),(1,3),(4,6),(5,7); t2 / -i*t2
        float2 d[8];
        {
            const float2 tb = make_float2(t2.y, -t2.x);  // -i*t2
            float2 v;
            v = cmul(t2, c[2]); d[0] = cadd(c[0], v); d[2] = csub(c[0], v);
            v = cmul(tb, c[3]); d[1] = cadd(c[1], v); d[3] = csub(c[1], v);
            v = cmul(t2, c[6]); d[4] = cadd(c[4], v); d[6] = csub(c[4], v);
            v = cmul(tb, c[7]); d[5] = cadd(c[5], v); d[7] = csub(c[5], v);
        }
        // stage 3 (len 4L): pairs (m, m+4); factors t4 * w8^m
        {
            const float2 f1 = make_float2(RQ * (t4.x + t4.y), RQ * (t4.y - t4.x));   // t4*(1-i)r
            const float2 f2 = make_float2(t4.y, -t4.x);                               // t4*(-i)
            const float2 f3 = make_float2(RQ * (t4.y - t4.x), -RQ * (t4.x + t4.y));  // t4*(-1-i)r
            float2 v;
            v = cmul(t4, d[4]); buf[swz<S>(p)]             = cadd(d[0], v); buf[swz<S>(p + 4*(L/2))] = csub(d[0], v);
            v = cmul(f1, d[5]); buf[swz<S>(p + 1*(L/2))]   = cadd(d[1], v); buf[swz<S>(p + 5*(L/2))] = csub(d[1], v);
            v = cmul(f2, d[6]); buf[swz<S>(p + 2*(L/2))]   = cadd(d[2], v); buf[swz<S>(p + 6*(L/2))] = csub(d[2], v);
            v = cmul(f3, d[7]); buf[swz<S>(p + 3*(L/2))]   = cadd(d[3], v); buf[swz<S>(p + 7*(L/2))] = csub(d[3], v);
        }
    }
}

// ---------------------------------------------------------------------------
// Packed complex FFT (z = x + i*x_hat) over all frames of one scale.
// Load fuses windowing + the first THREE stages (8-point DFT, trivial
// twiddles); then radix-8/radix-4 SMEM passes. XOR bank swizzle on buf.
// TPF = NFFT/8; frame-scoped synchronization (warp-level for N<=256).
// ---------------------------------------------------------------------------
template<int NFFT, int OFF>
__device__ __forceinline__ void stft_body(const float* __restrict__ x,
                                          const float* __restrict__ xh,
                                          int blk, char* raw) {
    constexpr int HOP   = NFFT / 4;
    constexpr int PAD   = NFFT / 2;
    constexpr int T     = 1 + NSAMP / HOP;
    constexpr int TOTAL = BATCH * T;
    constexpr int F     = NFFT / 2 + 1;
    constexpr int LOG2N = ilog2c(NFFT);
    constexpr int TPB   = 256;
    constexpr int TPF   = (NFFT / 8 > TPB) ? TPB : (NFFT / 8);  // threads per frame
    constexpr int FPB   = TPB / TPF;                   // frames per block
    constexpr int KPT   = (F + TPF - 1) / TPF;         // freq bins per thread (unpack)
    constexpr int BUFSZ = FPB * NFFT;                  // == 2048 for all scales
    static_assert(BUFSZ == 2048, "layout assumes BUFSZ==2048");
    constexpr int S     = ilog2c(BUFSZ) - 4;

    float2* buf  = (float2*)raw;
    float2* tw   = (float2*)(raw + 16384);
    float*  win  = (float*)(raw + 16384 + 4 * NFFT);
    float*  red1 = (float*)(raw + 16384 + 8 * NFFT);
    float*  red2 = (float*)(raw + 16384 + 8 * NFFT + 4 * F);

    const int tid  = threadIdx.x;
    const int slot = tid / TPF;
    const int ltid = tid % TPF;
    const int base = slot * NFFT;

    auto sw = [](int i) { return swz<S>(i); };

    // Frame-scoped sync.
    auto fsync = [&]() {
        if constexpr (TPF <= 32) { __syncwarp(); }
        else if constexpr (TPF >= TPB) { __syncthreads(); }
        else { asm volatile("bar.sync %0, %1;" :: "r"(slot + 1), "r"(TPF) : "memory"); }
    };

    // Twiddles: tw[t] = exp(-2*pi*i*t/N). Window: periodic hann / sqrt(0.375*N).
    const float rnorm = rsqrtf(0.375f * (float)NFFT);
    for (int t = tid; t < NFFT / 2; t += TPB) {
        float s, c;
        sincospif(2.0f * (float)t / (float)NFFT, &s, &c);
        tw[t] = make_float2(c, -s);
    }
    for (int t = tid; t < NFFT; t += TPB) {
        win[t] = (0.5f - 0.5f * cospif(2.0f * (float)t / (float)NFFT)) * rnorm;
    }
    for (int t = tid; t < F; t += TPB) { red1[t] = 0.0f; red2[t] = 0.0f; }

    float acc1[KPT], acc2[KPT];
#pragma unroll
    for (int r = 0; r < KPT; r++) { acc1[r] = 0.0f; acc2[r] = 0.0f; }

    __syncthreads();

    for (int fb = blk * FPB; fb < TOTAL; fb += BLKS_PER_SCALE * FPB) {
        const int gf = fb + slot;
        const bool valid = (gf < TOTAL);

        // Load + window + 8-point DFT (stages 2,4,8 with trivial twiddles).
        // Thread reads samples idx + m*N/8 (coalesced), writes 8 consecutive
        // outputs at group g = bitrev_{LOG2N-3}(idx).
        if (valid) {
            const int bb = gf / T;
            const int t0 = gf - bb * T;
            const int start = t0 * HOP - PAD;
            const float* xb  = x  + bb * NSAMP;
            const float* xhb = xh + bb * NSAMP;
            const int idx = ltid;                 // [0, N/8), TPF == N/8
            const int g   = (int)(__brev((unsigned)idx) >> (32 - (LOG2N - 3)));
            float2 a[8];
#pragma unroll
            for (int m = 0; m < 8; m++) {
                const int tt = idx + m * (NFFT / 8);
                int s = start + tt;
                s = (s < 0) ? -s : s;                        // reflect left
                s = (s >= NSAMP) ? (2 * NSAMP - 2 - s) : s;  // reflect right
                const float wv = win[tt];
                a[m] = make_float2(xb[s] * wv, xhb[s] * wv);
            }
            // E = DFT4(a0,a2,a4,a6), O = DFT4(a1,a3,a5,a7)
            const float2 t0v = cadd(a[0], a[4]), t1v = csub(a[0], a[4]);
            const float2 t2v = cadd(a[2], a[6]), t3v = csub(a[2], a[6]);
            const float2 E0 = cadd(t0v, t2v), E2 = csub(t0v, t2v);
            const float2 E1 = make_float2(t1v.x + t3v.y, t1v.y - t3v.x);
            const float2 E3 = make_float2(t1v.x - t3v.y, t1v.y + t3v.x);
            const float2 u0 = cadd(a[1], a[5]), u1 = csub(a[1], a[5]);
            const float2 u2 = cadd(a[3], a[7]), u3 = csub(a[3], a[7]);
            const float2 O0 = cadd(u0, u2), O2 = csub(u0, u2);
            const float2 O1 = make_float2(u1.x + u3.y, u1.y - u3.x);
            const float2 O3 = make_float2(u1.x - u3.y, u1.y + u3.x);
            const float2 w1O1 = make_float2(RQ * (O1.x + O1.y), RQ * (O1.y - O1.x));   // (1-i)r*O1
            const float2 w2O2 = make_float2(O2.y, -O2.x);                               // -i*O2
            const float2 w3O3 = make_float2(RQ * (O3.y - O3.x), -RQ * (O3.x + O3.y));  // (-1-i)r*O3
            const int wb = base + 8 * g;
            buf[sw(wb + 0)] = cadd(E0, O0);   buf[sw(wb + 4)] = csub(E0, O0);
            buf[sw(wb + 1)] = cadd(E1, w1O1); buf[sw(wb + 5)] = csub(E1, w1O1);
            buf[sw(wb + 2)] = cadd(E2, w2O2); buf[sw(wb + 6)] = csub(E2, w2O2);
            buf[sw(wb + 3)] = cadd(E3, w3O3); buf[sw(wb + 7)] = csub(E3, w3O3);
        }
        fsync();

        // Remaining stages: radix-8 / radix-4 passes.
        if constexpr (LOG2N == 5) {
            radix4_pass<NFFT, 16, TPF, S>(buf, tw, base, ltid); fsync();
        } else if constexpr (LOG2N == 6) {
            radix8_pass<NFFT, 16, TPF, S>(buf, tw, base, ltid); fsync();
        } else if constexpr (LOG2N == 7) {
            radix4_pass<NFFT, 16, TPF, S>(buf, tw, base, ltid); fsync();
            radix4_pass<NFFT, 64, TPF, S>(buf, tw, base, ltid); fsync();
        } else if constexpr (LOG2N == 8) {
            radix8_pass<NFFT, 16, TPF, S>(buf, tw, base, ltid); fsync();
            radix4_pass<NFFT, 128, TPF, S>(buf, tw, base, ltid); fsync();
        } else if constexpr (LOG2N == 9) {
            radix8_pass<NFFT, 16, TPF, S>(buf, tw, base, ltid); fsync();
            radix8_pass<NFFT, 128, TPF, S>(buf, tw, base, ltid); fsync();
        } else if constexpr (LOG2N == 10) {
            radix8_pass<NFFT, 16, TPF, S>(buf, tw, base, ltid); fsync();
            radix4_pass<NFFT, 128, TPF, S>(buf, tw, base, ltid); fsync();
            radix4_pass<NFFT, 512, TPF, S>(buf, tw, base, ltid); fsync();
        } else {
            radix8_pass<NFFT, 16, TPF, S>(buf, tw, base, ltid); fsync();
            radix8_pass<NFFT, 128, TPF, S>(buf, tw, base, ltid); fsync();
            radix4_pass<NFFT, 1024, TPF, S>(buf, tw, base, ltid); fsync();
        }

        // Unpack X (from x) and Xh (from x_hat), accumulate stats
        if (valid) {
#pragma unroll
            for (int r = 0; r < KPT; r++) {
                const int k = ltid + r * TPF;
                if (k <= NFFT / 2) {
                    const float2 zk = buf[sw(base + k)];
                    const float2 zn = buf[sw(base + ((NFFT - k) & (NFFT - 1)))];
                    const float ar = 0.5f * (zk.x + zn.x);
                    const float ai = 0.5f * (zk.y - zn.y);
                    const float br = 0.5f * (zk.y + zn.y);
                    const float bi = 0.5f * (zn.x - zk.x);
                    const float magA = sqrtf(ar * ar + ai * ai);
                    const float magB = sqrtf(br * br + bi * bi);
                    const float d = magB - magA;          // |Xh| - |X|
                    acc1[r] += fabsf(d);
                    acc2[r] += d * d;
                }
            }
        }
        fsync();   // protect buf before next load (frame-scoped)
    }

    // Block reduce: registers -> shared float
#pragma unroll
    for (int r = 0; r < KPT; r++) {
        const int k = ltid + r * TPF;
        if (k <= NFFT / 2) {
            atomicAdd(&red1[k], acc1[r]);
            atomicAdd(&red2[k], acc2[r]);
        }
    }
    __syncthreads();

    for (int k = tid; k < F; k += TPB) {
        atomicAdd(&g_s1[OFF + k], (double)red1[k]);
        atomicAdd(&g_s2[OFF + k], (double)red2[k]);
    }
}

// All 7 scales in one launch; min 4 blocks/SM (forces <=64 regs, occ ~50%).
__global__ void __launch_bounds__(256, 4)
fused_stft(const float* __restrict__ x, const float* __restrict__ xh) {
    extern __shared__ char raw[];
    const int b = blockIdx.x;
    if      (b < 1 * BLKS_PER_SCALE) stft_body<  32,    0>(x, xh, b - 0 * BLKS_PER_SCALE, raw);
    else if (b < 2 * BLKS_PER_SCALE) stft_body<  64,   17>(x, xh, b - 1 * BLKS_PER_SCALE, raw);
    else if (b < 3 * BLKS_PER_SCALE) stft_body< 128,   50>(x, xh, b - 2 * BLKS_PER_SCALE, raw);
    else if (b < 4 * BLKS_PER_SCALE) stft_body< 256,  115>(x, xh, b - 3 * BLKS_PER_SCALE, raw);
    else if (b < 5 * BLKS_PER_SCALE) stft_body< 512,  244>(x, xh, b - 4 * BLKS_PER_SCALE, raw);
    else if (b < 6 * BLKS_PER_SCALE) stft_body<1024,  501>(x, xh, b - 5 * BLKS_PER_SCALE, raw);
    else                             stft_body<2048, 1014>(x, xh, b - 6 * BLKS_PER_SCALE, raw);
}

// ---------------------------------------------------------------------------
// Init: zero accumulators + compute mel band edges (bit-identical decision
// logic to the verified rel_err=0 version: strict f_pts[m] < f*step <
// f_pts[m+2], Nyquist decided by the flipped libdevice pow round-trip).
// ---------------------------------------------------------------------------
__global__ void __launch_bounds__(256) init_kernel() {
    const int s   = blockIdx.x;   // 0..6
    const int tid = threadIdx.x;
    const int NFFT = 32 << s;

    for (int i = s * 256 + tid; i < TOTF; i += 7 * 256) { g_s1[i] = 0.0; g_s2[i] = 0.0; }
    if (s == 0 && tid == 0) { g_acc = 0.0; g_done = 0; }

    bool keep = false;
    if (tid < 64) {
        const int m = tid;
        const int F = NFFT / 2 + 1;
        const double step = 12000.0 / (double)(F - 1);
        const double melmax = 2595.0 * log10(1.0 + 12000.0 / 700.0);

        const double e65  = (melmax * 65.0 / 65.0) / 2595.0;
        const double hi65 = 700.0 * (pow(10.0, opaque_d(e65)) - 1.0);
        const bool   nyq_in = !(hi65 > 12000.0);

        int a[2], b[2];   // [0] = band m, [1] = band m-1
        for (int q = 0; q < 2; q++) {
            const int mm = m - q;
            if (mm < 0) { a[q] = 0; b[q] = 0; continue; }
            const double lo = 700.0 * (pow(10.0, opaque_d(melmax * (double)mm / 65.0) / 2595.0) - 1.0);
            int a0 = (int)floor(lo / step); if ((double)a0 * step <= lo) a0++;  // first f: f*step > lo
            if (a0 < 0) a0 = 0;
            int b0;
            if (mm + 2 == 65) {
                b0 = nyq_in ? F : (F - 1);
            } else {
                const double hi = 700.0 * (pow(10.0, opaque_d(melmax * (double)(mm + 2) / 65.0) / 2595.0) - 1.0);
                b0 = (int)floor(hi / step); if ((double)b0 * step <  hi) b0++;  // last f+1: f*step < hi
                if (b0 > F) b0 = F;
            }
            a[q] = a0; b[q] = b0;
        }
        const bool nonempty = (b[0] > a[0]);
        const bool dup = (m > 0) && (a[0] == a[1]) && (b[0] == b[1]) && nonempty;
        keep = nonempty && !dup;
        g_ab[s * 64 + m] = keep ? make_int2(a[0], b[0]) : make_int2(0, 0);
    }
    const int cnt = __syncthreads_count(keep ? 1 : 0);
    if (tid == 0) g_nb[s] = cnt;
}

// ---------------------------------------------------------------------------
// Loss: 7 blocks (one per scale). One warp per band candidate (strided);
// lane-parallel slice sums + shuffle reduce. Last-finisher writes output.
// ---------------------------------------------------------------------------
__global__ void __launch_bounds__(256) loss_kernel(float* out) {
    const int s    = blockIdx.x;
    const int tid  = threadIdx.x;
    const int w    = tid >> 5;
    const int lane = tid & 31;

    __shared__ double ssum;
    if (tid == 0) ssum = 0.0;
    __syncthreads();

    for (int cand = w; cand < 64; cand += 8) {
        const int2 ab = g_ab[s * 64 + cand];
        if (ab.y > ab.x) {
            double p1 = 0.0, p2 = 0.0;
            for (int f = ab.x + lane; f < ab.y; f += 32) {
                p1 += g_s1[c_soff[s] + f];
                p2 += g_s2[c_soff[s] + f];
            }
#pragma unroll
            for (int o = 16; o > 0; o >>= 1) {
                p1 += __shfl_down_sync(0xffffffffu, p1, o);
                p2 += __shfl_down_sync(0xffffffffu, p2, o);
            }
            if (lane == 0) {
                const double cnt = (double)(ab.y - ab.x) * (double)BATCH * (double)c_T[s];
                const double val = p1 / cnt + sqrt(p2 / cnt + 1e-8);
                atomicAdd(&ssum, val);
            }
        }
    }
    __syncthreads();

    if (tid == 0) {
        const double contrib = ssum / (double)g_nb[s] / 7.0;
        atomicAdd(&g_acc, contrib);
        __threadfence();
        const int old = atomicAdd(&g_done, 1);
        if (old == 6) {
            out[0] = (float)(*(volatile double*)&g_acc);
        }
    }
}

extern "C" void kernel_launch(void* const* d_in, const int* in_sizes, int n_in,
                              void* d_out, int out_size) {
    const float* xh = (const float*)d_in[0];   // x_hat
    const float* x  = (const float*)d_in[1];   // x

    init_kernel<<<7, 256>>>();
    fused_stft<<<7 * BLKS_PER_SCALE, 256, SMEM_DYN>>>(x, xh);
    loss_kernel<<<7, 256>>>((float*)d_out);
}

// round 10
// speedup vs baseline: 2.2715x; 1.0107x over previous
#include <cuda_runtime.h>
#include <math.h>

#define BATCH 16
#define NSAMP 72000
#define TOTF  2039   // 17+33+65+129+257+513+1025

// One fused scratch blob -> single memset clears everything:
// [0,TOTF) = s1, [TOTF,2*TOTF) = s2, [2*TOTF] = acc, [2*TOTF+1] = done flag.
__device__ double g_blob[2 * TOTF + 2];
#define g_s1 (g_blob)
#define g_s2 (g_blob + TOTF)

__host__ __device__ constexpr int ilog2c(int n) { return (n <= 1) ? 0 : 1 + ilog2c(n >> 1); }

// Blocks runtime constant folding while preserving exact double bits.
__device__ __forceinline__ double opaque_d(double x) { volatile double t = x; return t; }

__device__ __forceinline__ float2 cadd(float2 a, float2 b) { return make_float2(a.x + b.x, a.y + b.y); }
__device__ __forceinline__ float2 csub(float2 a, float2 b) { return make_float2(a.x - b.x, a.y - b.y); }
__device__ __forceinline__ float2 cmul(float2 a, float2 b) {
    return make_float2(a.x * b.x - a.y * b.y, a.x * b.y + a.y * b.x);
}

#define BLKS_PER_SCALE 740
#define SMEM_DYN (16384 + 8 * 2048 + 8 * 1032)
#define RQ 0.70710678118654752440f

__device__ __constant__ int c_soff[7] = {0, 17, 50, 115, 244, 501, 1014};
__device__ __constant__ int c_T[7]    = {9001, 4501, 2251, 1126, 563, 282, 141};

template<int S>
__device__ __forceinline__ int swz(int i) { return i ^ (((i >> S) ^ (i >> 4)) & 15); }

// Radix-4 SMEM pass: stages (L, 2L). t2 = w_{2L}^j from LDS, w_L^j = t2^2.
template<int NFFT, int L, int TPF, int S>
__device__ __forceinline__ void radix4_pass(float2* buf, const float2* tw, int base, int ltid) {
    constexpr int BPT = (NFFT / 4) / TPF;
#pragma unroll
    for (int r = 0; r < BPT; r++) {
        const int idx = ltid + r * TPF;
        const int j   = idx & (L / 2 - 1);
        const int g   = idx / (L / 2);
        const int p   = base + g * (2 * L) + j;
        float2 a0 = buf[swz<S>(p)];
        float2 a1 = buf[swz<S>(p + L / 2)];
        float2 a2 = buf[swz<S>(p + L)];
        float2 a3 = buf[swz<S>(p + 3 * L / 2)];
        const float2 t2 = tw[j * (NFFT / (2 * L))];  // w_{2L}^j
        const float2 t1 = cmul(t2, t2);              // w_L^j
        const float2 u1 = cmul(t1, a1), u3 = cmul(t1, a3);
        const float2 c0 = cadd(a0, u1), c1 = csub(a0, u1);
        const float2 c2 = cadd(a2, u3), c3 = csub(a2, u3);
        const float2 v2 = cmul(t2, c2), v3 = cmul(t2, c3);
        buf[swz<S>(p)]             = cadd(c0, v2);
        buf[swz<S>(p + L)]         = csub(c0, v2);
        buf[swz<S>(p + L / 2)]     = make_float2(c1.x + v3.y, c1.y - v3.x);  // c1 - i*v3
        buf[swz<S>(p + 3 * L / 2)] = make_float2(c1.x - v3.y, c1.y + v3.x);  // c1 + i*v3
    }
}

// Radix-8 SMEM pass: stages (L, 2L, 4L) in one round trip.
// t4 = w_{4L}^j (one LDS); t2 = t4^2, t1 = t4^4 (exact identities).
// Stage-2 odd-slot twiddle = -i*t2; stage-3 factors = t4 * w8^m.
template<int NFFT, int L, int TPF, int S>
__device__ __forceinline__ void radix8_pass(float2* buf, const float2* tw, int base, int ltid) {
    constexpr int BPT = (NFFT / 8) / TPF;
#pragma unroll
    for (int r = 0; r < BPT; r++) {
        const int idx = ltid + r * TPF;
        const int j   = idx & (L / 2 - 1);
        const int g   = idx / (L / 2);
        const int p   = base + g * (4 * L) + j;
        float2 b[8];
#pragma unroll
        for (int m = 0; m < 8; m++) b[m] = buf[swz<S>(p + m * (L / 2))];
        const float2 t4 = tw[j * (NFFT / (4 * L))];  // w_{4L}^j
        const float2 t2 = cmul(t4, t4);              // w_{2L}^j
        const float2 t1 = cmul(t2, t2);              // w_L^j
        // stage 1 (len L): pairs (0,1),(2,3),(4,5),(6,7), twiddle t1
        float2 c[8];
#pragma unroll
        for (int m = 0; m < 4; m++) {
            const float2 u = cmul(t1, b[2 * m + 1]);
            c[2 * m]     = cadd(b[2 * m], u);
            c[2 * m + 1] = csub(b[2 * m], u);
        }
        // stage 2 (len 2L): pairs (0,2),(1,3),(4,6),(5,7); t2 / -i*t2
        float2 d[8];
        {
            const float2 tb = make_float2(t2.y, -t2.x);  // -i*t2
            float2 v;
            v = cmul(t2, c[2]); d[0] = cadd(c[0], v); d[2] = csub(c[0], v);
            v = cmul(tb, c[3]); d[1] = cadd(c[1], v); d[3] = csub(c[1], v);
            v = cmul(t2, c[6]); d[4] = cadd(c[4], v); d[6] = csub(c[4], v);
            v = cmul(tb, c[7]); d[5] = cadd(c[5], v); d[7] = csub(c[5], v);
        }
        // stage 3 (len 4L): pairs (m, m+4); factors t4 * w8^m
        {
            const float2 f1 = make_float2(RQ * (t4.x + t4.y), RQ * (t4.y - t4.x));   // t4*(1-i)r
            const float2 f2 = make_float2(t4.y, -t4.x);                               // t4*(-i)
            const float2 f3 = make_float2(RQ * (t4.y - t4.x), -RQ * (t4.x + t4.y));  // t4*(-1-i)r
            float2 v;
            v = cmul(t4, d[4]); buf[swz<S>(p)]             = cadd(d[0], v); buf[swz<S>(p + 4*(L/2))] = csub(d[0], v);
            v = cmul(f1, d[5]); buf[swz<S>(p + 1*(L/2))]   = cadd(d[1], v); buf[swz<S>(p + 5*(L/2))] = csub(d[1], v);
            v = cmul(f2, d[6]); buf[swz<S>(p + 2*(L/2))]   = cadd(d[2], v); buf[swz<S>(p + 6*(L/2))] = csub(d[2], v);
            v = cmul(f3, d[7]); buf[swz<S>(p + 3*(L/2))]   = cadd(d[3], v); buf[swz<S>(p + 7*(L/2))] = csub(d[3], v);
        }
    }
}

// ---------------------------------------------------------------------------
// Packed complex FFT (z = x + i*x_hat) over all frames of one scale.
// Load fuses windowing + the first THREE stages (8-point DFT, trivial
// twiddles); then radix-8/radix-4 SMEM passes. XOR bank swizzle on buf.
// TPF = NFFT/8; frame-scoped synchronization (warp-level for N<=256).
// ---------------------------------------------------------------------------
template<int NFFT, int OFF>
__device__ __forceinline__ void stft_body(const float* __restrict__ x,
                                          const float* __restrict__ xh,
                                          int blk, char* raw) {
    constexpr int HOP   = NFFT / 4;
    constexpr int PAD   = NFFT / 2;
    constexpr int T     = 1 + NSAMP / HOP;
    constexpr int TOTAL = BATCH * T;
    constexpr int F     = NFFT / 2 + 1;
    constexpr int LOG2N = ilog2c(NFFT);
    constexpr int TPB   = 256;
    constexpr int TPF   = (NFFT / 8 > TPB) ? TPB : (NFFT / 8);  // threads per frame
    constexpr int FPB   = TPB / TPF;                   // frames per block
    constexpr int KPT   = (F + TPF - 1) / TPF;         // freq bins per thread (unpack)
    constexpr int BUFSZ = FPB * NFFT;                  // == 2048 for all scales
    static_assert(BUFSZ == 2048, "layout assumes BUFSZ==2048");
    constexpr int S     = ilog2c(BUFSZ) - 4;

    float2* buf  = (float2*)raw;
    float2* tw   = (float2*)(raw + 16384);
    float*  win  = (float*)(raw + 16384 + 4 * NFFT);
    float*  red1 = (float*)(raw + 16384 + 8 * NFFT);
    float*  red2 = (float*)(raw + 16384 + 8 * NFFT + 4 * F);

    const int tid  = threadIdx.x;
    const int slot = tid / TPF;
    const int ltid = tid % TPF;
    const int base = slot * NFFT;

    auto sw = [](int i) { return swz<S>(i); };

    // Frame-scoped sync.
    auto fsync = [&]() {
        if constexpr (TPF <= 32) { __syncwarp(); }
        else if constexpr (TPF >= TPB) { __syncthreads(); }
        else { asm volatile("bar.sync %0, %1;" :: "r"(slot + 1), "r"(TPF) : "memory"); }
    };

    // Twiddles: tw[t] = exp(-2*pi*i*t/N). Window: periodic hann / sqrt(0.375*N).
    const float rnorm = rsqrtf(0.375f * (float)NFFT);
    for (int t = tid; t < NFFT / 2; t += TPB) {
        float s, c;
        sincospif(2.0f * (float)t / (float)NFFT, &s, &c);
        tw[t] = make_float2(c, -s);
    }
    for (int t = tid; t < NFFT; t += TPB) {
        win[t] = (0.5f - 0.5f * cospif(2.0f * (float)t / (float)NFFT)) * rnorm;
    }
    for (int t = tid; t < F; t += TPB) { red1[t] = 0.0f; red2[t] = 0.0f; }

    float acc1[KPT], acc2[KPT];
#pragma unroll
    for (int r = 0; r < KPT; r++) { acc1[r] = 0.0f; acc2[r] = 0.0f; }

    __syncthreads();

    for (int fb = blk * FPB; fb < TOTAL; fb += BLKS_PER_SCALE * FPB) {
        const int gf = fb + slot;
        const bool valid = (gf < TOTAL);

        // Load + window + 8-point DFT (stages 2,4,8 with trivial twiddles).
        // Thread reads samples idx + m*N/8 (coalesced), writes 8 consecutive
        // outputs at group g = bitrev_{LOG2N-3}(idx).
        if (valid) {
            const int bb = gf / T;
            const int t0 = gf - bb * T;
            const int start = t0 * HOP - PAD;
            const float* xb  = x  + bb * NSAMP;
            const float* xhb = xh + bb * NSAMP;
            const int idx = ltid;                 // [0, N/8), TPF == N/8
            const int g   = (int)(__brev((unsigned)idx) >> (32 - (LOG2N - 3)));
            float2 a[8];
#pragma unroll
            for (int m = 0; m < 8; m++) {
                const int tt = idx + m * (NFFT / 8);
                int s = start + tt;
                s = (s < 0) ? -s : s;                        // reflect left
                s = (s >= NSAMP) ? (2 * NSAMP - 2 - s) : s;  // reflect right
                const float wv = win[tt];
                a[m] = make_float2(xb[s] * wv, xhb[s] * wv);
            }
            // E = DFT4(a0,a2,a4,a6), O = DFT4(a1,a3,a5,a7)
            const float2 t0v = cadd(a[0], a[4]), t1v = csub(a[0], a[4]);
            const float2 t2v = cadd(a[2], a[6]), t3v = csub(a[2], a[6]);
            const float2 E0 = cadd(t0v, t2v), E2 = csub(t0v, t2v);
            const float2 E1 = make_float2(t1v.x + t3v.y, t1v.y - t3v.x);
            const float2 E3 = make_float2(t1v.x - t3v.y, t1v.y + t3v.x);
            const float2 u0 = cadd(a[1], a[5]), u1 = csub(a[1], a[5]);
            const float2 u2 = cadd(a[3], a[7]), u3 = csub(a[3], a[7]);
            const float2 O0 = cadd(u0, u2), O2 = csub(u0, u2);
            const float2 O1 = make_float2(u1.x + u3.y, u1.y - u3.x);
            const float2 O3 = make_float2(u1.x - u3.y, u1.y + u3.x);
            const float2 w1O1 = make_float2(RQ * (O1.x + O1.y), RQ * (O1.y - O1.x));   // (1-i)r*O1
            const float2 w2O2 = make_float2(O2.y, -O2.x);                               // -i*O2
            const float2 w3O3 = make_float2(RQ * (O3.y - O3.x), -RQ * (O3.x + O3.y));  // (-1-i)r*O3
            const int wb = base + 8 * g;
            buf[sw(wb + 0)] = cadd(E0, O0);   buf[sw(wb + 4)] = csub(E0, O0);
            buf[sw(wb + 1)] = cadd(E1, w1O1); buf[sw(wb + 5)] = csub(E1, w1O1);
            buf[sw(wb + 2)] = cadd(E2, w2O2); buf[sw(wb + 6)] = csub(E2, w2O2);
            buf[sw(wb + 3)] = cadd(E3, w3O3); buf[sw(wb + 7)] = csub(E3, w3O3);
        }
        fsync();

        // Remaining stages: radix-8 / radix-4 passes.
        if constexpr (LOG2N == 5) {
            radix4_pass<NFFT, 16, TPF, S>(buf, tw, base, ltid); fsync();
        } else if constexpr (LOG2N == 6) {
            radix8_pass<NFFT, 16, TPF, S>(buf, tw, base, ltid); fsync();
        } else if constexpr (LOG2N == 7) {
            radix4_pass<NFFT, 16, TPF, S>(buf, tw, base, ltid); fsync();
            radix4_pass<NFFT, 64, TPF, S>(buf, tw, base, ltid); fsync();
        } else if constexpr (LOG2N == 8) {
            radix8_pass<NFFT, 16, TPF, S>(buf, tw, base, ltid); fsync();
            radix4_pass<NFFT, 128, TPF, S>(buf, tw, base, ltid); fsync();
        } else if constexpr (LOG2N == 9) {
            radix8_pass<NFFT, 16, TPF, S>(buf, tw, base, ltid); fsync();
            radix8_pass<NFFT, 128, TPF, S>(buf, tw, base, ltid); fsync();
        } else if constexpr (LOG2N == 10) {
            radix8_pass<NFFT, 16, TPF, S>(buf, tw, base, ltid); fsync();
            radix4_pass<NFFT, 128, TPF, S>(buf, tw, base, ltid); fsync();
            radix4_pass<NFFT, 512, TPF, S>(buf, tw, base, ltid); fsync();
        } else {
            radix8_pass<NFFT, 16, TPF, S>(buf, tw, base, ltid); fsync();
            radix8_pass<NFFT, 128, TPF, S>(buf, tw, base, ltid); fsync();
            radix4_pass<NFFT, 1024, TPF, S>(buf, tw, base, ltid); fsync();
        }

        // Unpack X (from x) and Xh (from x_hat), accumulate stats
        if (valid) {
#pragma unroll
            for (int r = 0; r < KPT; r++) {
                const int k = ltid + r * TPF;
                if (k <= NFFT / 2) {
                    const float2 zk = buf[sw(base + k)];
                    const float2 zn = buf[sw(base + ((NFFT - k) & (NFFT - 1)))];
                    const float ar = 0.5f * (zk.x + zn.x);
                    const float ai = 0.5f * (zk.y - zn.y);
                    const float br = 0.5f * (zk.y + zn.y);
                    const float bi = 0.5f * (zn.x - zk.x);
                    const float magA = sqrtf(ar * ar + ai * ai);
                    const float magB = sqrtf(br * br + bi * bi);
                    const float d = magB - magA;          // |Xh| - |X|
                    acc1[r] += fabsf(d);
                    acc2[r] += d * d;
                }
            }
        }
        fsync();   // protect buf before next load (frame-scoped)
    }

    // Block reduce: registers -> shared float
#pragma unroll
    for (int r = 0; r < KPT; r++) {
        const int k = ltid + r * TPF;
        if (k <= NFFT / 2) {
            atomicAdd(&red1[k], acc1[r]);
            atomicAdd(&red2[k], acc2[r]);
        }
    }
    __syncthreads();

    for (int k = tid; k < F; k += TPB) {
        atomicAdd(&g_s1[OFF + k], (double)red1[k]);
        atomicAdd(&g_s2[OFF + k], (double)red2[k]);
    }
}

// All 7 scales in one launch; min 4 blocks/SM (forces <=64 regs, occ ~50%).
__global__ void __launch_bounds__(256, 4)
fused_stft(const float* __restrict__ x, const float* __restrict__ xh) {
    extern __shared__ char raw[];
    const int b = blockIdx.x;
    if      (b < 1 * BLKS_PER_SCALE) stft_body<  32,    0>(x, xh, b - 0 * BLKS_PER_SCALE, raw);
    else if (b < 2 * BLKS_PER_SCALE) stft_body<  64,   17>(x, xh, b - 1 * BLKS_PER_SCALE, raw);
    else if (b < 3 * BLKS_PER_SCALE) stft_body< 128,   50>(x, xh, b - 2 * BLKS_PER_SCALE, raw);
    else if (b < 4 * BLKS_PER_SCALE) stft_body< 256,  115>(x, xh, b - 3 * BLKS_PER_SCALE, raw);
    else if (b < 5 * BLKS_PER_SCALE) stft_body< 512,  244>(x, xh, b - 4 * BLKS_PER_SCALE, raw);
    else if (b < 6 * BLKS_PER_SCALE) stft_body<1024,  501>(x, xh, b - 5 * BLKS_PER_SCALE, raw);
    else                             stft_body<2048, 1014>(x, xh, b - 6 * BLKS_PER_SCALE, raw);
}

// ---------------------------------------------------------------------------
// Loss: 7 blocks (one per scale). Threads 0-63 first compute the mel band
// edges into smem (bit-identical decision logic to the verified rel_err=0
// version: strict f_pts[m] < f*step < f_pts[m+2], Nyquist decided by the
// flipped libdevice pow round-trip). Then one warp per band candidate:
// lane-parallel slice sums + shuffle reduce. Last-finisher writes output.
// ---------------------------------------------------------------------------
__global__ void __launch_bounds__(256) loss_kernel(float* out) {
    const int s    = blockIdx.x;
    const int tid  = threadIdx.x;
    const int w    = tid >> 5;
    const int lane = tid & 31;
    const int NFFT = 32 << s;

    __shared__ int2   sab[64];
    __shared__ double ssum;
    if (tid == 0) ssum = 0.0;

    bool keep = false;
    if (tid < 64) {
        const int m = tid;
        const int F = NFFT / 2 + 1;
        const double step = 12000.0 / (double)(F - 1);
        const double melmax = 2595.0 * log10(1.0 + 12000.0 / 700.0);

        const double e65  = (melmax * 65.0 / 65.0) / 2595.0;
        const double hi65 = 700.0 * (pow(10.0, opaque_d(e65)) - 1.0);
        const bool   nyq_in = !(hi65 > 12000.0);

        int a[2], b[2];   // [0] = band m, [1] = band m-1
        for (int q = 0; q < 2; q++) {
            const int mm = m - q;
            if (mm < 0) { a[q] = 0; b[q] = 0; continue; }
            const double lo = 700.0 * (pow(10.0, opaque_d(melmax * (double)mm / 65.0) / 2595.0) - 1.0);
            int a0 = (int)floor(lo / step); if ((double)a0 * step <= lo) a0++;  // first f: f*step > lo
            if (a0 < 0) a0 = 0;
            int b0;
            if (mm + 2 == 65) {
                b0 = nyq_in ? F : (F - 1);
            } else {
                const double hi = 700.0 * (pow(10.0, opaque_d(melmax * (double)(mm + 2) / 65.0) / 2595.0) - 1.0);
                b0 = (int)floor(hi / step); if ((double)b0 * step <  hi) b0++;  // last f+1: f*step < hi
                if (b0 > F) b0 = F;
            }
            a[q] = a0; b[q] = b0;
        }
        const bool nonempty = (b[0] > a[0]);
        const bool dup = (m > 0) && (a[0] == a[1]) && (b[0] == b[1]) && nonempty;
        keep = nonempty && !dup;
        sab[m] = keep ? make_int2(a[0], b[0]) : make_int2(0, 0);
    }
    const int nb = __syncthreads_count(keep ? 1 : 0);

    for (int cand = w; cand < 64; cand += 8) {
        const int2 ab = sab[cand];
        if (ab.y > ab.x) {
            double p1 = 0.0, p2 = 0.0;
            for (int f = ab.x + lane; f < ab.y; f += 32) {
                p1 += g_s1[c_soff[s] + f];
                p2 += g_s2[c_soff[s] + f];
            }
#pragma unroll
            for (int o = 16; o > 0; o >>= 1) {
                p1 += __shfl_down_sync(0xffffffffu, p1, o);
                p2 += __shfl_down_sync(0xffffffffu, p2, o);
            }
            if (lane == 0) {
                const double cnt = (double)(ab.y - ab.x) * (double)BATCH * (double)c_T[s];
                const double val = p1 / cnt + sqrt(p2 / cnt + 1e-8);
                atomicAdd(&ssum, val);
            }
        }
    }
    __syncthreads();

    if (tid == 0) {
        double* acc  = g_blob + 2 * TOTF;
        int*    done = (int*)(g_blob + 2 * TOTF + 1);
        const double contrib = ssum / (double)nb / 7.0;
        atomicAdd(acc, contrib);
        __threadfence();
        const int old = atomicAdd(done, 1);
        if (old == 6) {
            out[0] = (float)(*(volatile double*)acc);
        }
    }
}

extern "C" void kernel_launch(void* const* d_in, const int* in_sizes, int n_in,
                              void* d_out, int out_size) {
    const float* xh = (const float*)d_in[0];   // x_hat
    const float* x  = (const float*)d_in[1];   // x

    void* pb = nullptr;
    cudaGetSymbolAddress(&pb, g_blob);
    cudaMemsetAsync(pb, 0, (2 * TOTF + 2) * sizeof(double));

    fused_stft<<<7 * BLKS_PER_SCALE, 256, SMEM_DYN>>>(x, xh);
    loss_kernel<<<7, 256>>>((float*)d_out);
}

// round 11
// speedup vs baseline: 2.2941x; 1.0099x over previous
#include <cuda_runtime.h>
#include <math.h>

#define BATCH 16
#define NSAMP 72000
#define TOTF  2039   // 17+33+65+129+257+513+1025

// One fused scratch blob -> single memset clears everything:
// [0,TOTF) = s1, [TOTF,2*TOTF) = s2, [2*TOTF] = acc, [2*TOTF+1] = done flag.
__device__ double g_blob[2 * TOTF + 2];
#define g_s1 (g_blob)
#define g_s2 (g_blob + TOTF)

__host__ __device__ constexpr int ilog2c(int n) { return (n <= 1) ? 0 : 1 + ilog2c(n >> 1); }

// Blocks runtime constant folding while preserving exact double bits.
__device__ __forceinline__ double opaque_d(double x) { volatile double t = x; return t; }

__device__ __forceinline__ float2 cadd(float2 a, float2 b) { return make_float2(a.x + b.x, a.y + b.y); }
__device__ __forceinline__ float2 csub(float2 a, float2 b) { return make_float2(a.x - b.x, a.y - b.y); }
__device__ __forceinline__ float2 cmul(float2 a, float2 b) {
    return make_float2(a.x * b.x - a.y * b.y, a.x * b.y + a.y * b.x);
}

#define BLKS_PER_SCALE 740
#define SMEM_DYN (16384 + 8 * 2048 + 8 * 1032)
#define RQ 0.70710678118654752440f

__device__ __constant__ int c_soff[7] = {0, 17, 50, 115, 244, 501, 1014};
__device__ __constant__ int c_T[7]    = {9001, 4501, 2251, 1126, 563, 282, 141};

template<int S>
__device__ __forceinline__ int swz(int i) { return i ^ (((i >> S) ^ (i >> 4)) & 15); }

// Radix-4 SMEM pass: stages (L, 2L). t2 = w_{2L}^j from LDS, w_L^j = t2^2.
template<int NFFT, int L, int TPF, int S>
__device__ __forceinline__ void radix4_pass(float2* buf, const float2* tw, int base, int ltid) {
    constexpr int BPT = (NFFT / 4) / TPF;
#pragma unroll
    for (int r = 0; r < BPT; r++) {
        const int idx = ltid + r * TPF;
        const int j   = idx & (L / 2 - 1);
        const int g   = idx / (L / 2);
        const int p   = base + g * (2 * L) + j;
        float2 a0 = buf[swz<S>(p)];
        float2 a1 = buf[swz<S>(p + L / 2)];
        float2 a2 = buf[swz<S>(p + L)];
        float2 a3 = buf[swz<S>(p + 3 * L / 2)];
        const float2 t2 = tw[j * (NFFT / (2 * L))];  // w_{2L}^j
        const float2 t1 = cmul(t2, t2);              // w_L^j
        const float2 u1 = cmul(t1, a1), u3 = cmul(t1, a3);
        const float2 c0 = cadd(a0, u1), c1 = csub(a0, u1);
        const float2 c2 = cadd(a2, u3), c3 = csub(a2, u3);
        const float2 v2 = cmul(t2, c2), v3 = cmul(t2, c3);
        buf[swz<S>(p)]             = cadd(c0, v2);
        buf[swz<S>(p + L)]         = csub(c0, v2);
        buf[swz<S>(p + L / 2)]     = make_float2(c1.x + v3.y, c1.y - v3.x);  // c1 - i*v3
        buf[swz<S>(p + 3 * L / 2)] = make_float2(c1.x - v3.y, c1.y + v3.x);  // c1 + i*v3
    }
}

// Radix-8 SMEM pass: stages (L, 2L, 4L) in one round trip.
// t4 = w_{4L}^j (one LDS); t2 = t4^2, t1 = t4^4 (exact identities).
// Stage-2 odd-slot twiddle = -i*t2; stage-3 factors = t4 * w8^m.
template<int NFFT, int L, int TPF, int S>
__device__ __forceinline__ void radix8_pass(float2* buf, const float2* tw, int base, int ltid) {
    constexpr int BPT = (NFFT / 8) / TPF;
#pragma unroll
    for (int r = 0; r < BPT; r++) {
        const int idx = ltid + r * TPF;
        const int j   = idx & (L / 2 - 1);
        const int g   = idx / (L / 2);
        const int p   = base + g * (4 * L) + j;
        float2 b[8];
#pragma unroll
        for (int m = 0; m < 8; m++) b[m] = buf[swz<S>(p + m * (L / 2))];
        const float2 t4 = tw[j * (NFFT / (4 * L))];  // w_{4L}^j
        const float2 t2 = cmul(t4, t4);              // w_{2L}^j
        const float2 t1 = cmul(t2, t2);              // w_L^j
        // stage 1 (len L): pairs (0,1),(2,3),(4,5),(6,7), twiddle t1
        float2 c[8];
#pragma unroll
        for (int m = 0; m < 4; m++) {
            const float2 u = cmul(t1, b[2 * m + 1]);
            c[2 * m]     = cadd(b[2 * m], u);
            c[2 * m + 1] = csub(b[2 * m], u);
        }
        // stage 2 (len 2L): pairs (0,2),(1,3),(4,6),(5,7); t2 / -i*t2
        float2 d[8];
        {
            const float2 tb = make_float2(t2.y, -t2.x);  // -i*t2
            float2 v;
            v = cmul(t2, c[2]); d[0] = cadd(c[0], v); d[2] = csub(c[0], v);
            v = cmul(tb, c[3]); d[1] = cadd(c[1], v); d[3] = csub(c[1], v);
            v = cmul(t2, c[6]); d[4] = cadd(c[4], v); d[6] = csub(c[4], v);
            v = cmul(tb, c[7]); d[5] = cadd(c[5], v); d[7] = csub(c[5], v);
        }
        // stage 3 (len 4L): pairs (m, m+4); factors t4 * w8^m
        {
            const float2 f1 = make_float2(RQ * (t4.x + t4.y), RQ * (t4.y - t4.x));   // t4*(1-i)r
            const float2 f2 = make_float2(t4.y, -t4.x);                               // t4*(-i)
            const float2 f3 = make_float2(RQ * (t4.y - t4.x), -RQ * (t4.x + t4.y));  // t4*(-1-i)r
            float2 v;
            v = cmul(t4, d[4]); buf[swz<S>(p)]             = cadd(d[0], v); buf[swz<S>(p + 4*(L/2))] = csub(d[0], v);
            v = cmul(f1, d[5]); buf[swz<S>(p + 1*(L/2))]   = cadd(d[1], v); buf[swz<S>(p + 5*(L/2))] = csub(d[1], v);
            v = cmul(f2, d[6]); buf[swz<S>(p + 2*(L/2))]   = cadd(d[2], v); buf[swz<S>(p + 6*(L/2))] = csub(d[2], v);
            v = cmul(f3, d[7]); buf[swz<S>(p + 3*(L/2))]   = cadd(d[3], v); buf[swz<S>(p + 7*(L/2))] = csub(d[3], v);
        }
    }
}

// ---------------------------------------------------------------------------
// Packed complex FFT (z = x + i*x_hat) over all frames of one scale.
// Load fuses windowing + the first THREE stages (8-point DFT, trivial
// twiddles); then radix-8/radix-4 SMEM passes. XOR bank swizzle on buf.
// TPF = NFFT/8; frame-scoped synchronization (warp-level for N<=256).
// ---------------------------------------------------------------------------
template<int NFFT, int OFF>
__device__ __forceinline__ void stft_body(const float* __restrict__ x,
                                          const float* __restrict__ xh,
                                          int blk, char* raw) {
    constexpr int HOP   = NFFT / 4;
    constexpr int PAD   = NFFT / 2;
    constexpr int T     = 1 + NSAMP / HOP;
    constexpr int TOTAL = BATCH * T;
    constexpr int F     = NFFT / 2 + 1;
    constexpr int LOG2N = ilog2c(NFFT);
    constexpr int TPB   = 256;
    constexpr int TPF   = (NFFT / 8 > TPB) ? TPB : (NFFT / 8);  // threads per frame
    constexpr int FPB   = TPB / TPF;                   // frames per block
    constexpr int KPT   = (F + TPF - 1) / TPF;         // freq bins per thread (unpack)
    constexpr int BUFSZ = FPB * NFFT;                  // == 2048 for all scales
    static_assert(BUFSZ == 2048, "layout assumes BUFSZ==2048");
    constexpr int S     = ilog2c(BUFSZ) - 4;

    float2* buf  = (float2*)raw;
    float2* tw   = (float2*)(raw + 16384);
    float*  win  = (float*)(raw + 16384 + 4 * NFFT);
    float*  red1 = (float*)(raw + 16384 + 8 * NFFT);
    float*  red2 = (float*)(raw + 16384 + 8 * NFFT + 4 * F);

    const int tid  = threadIdx.x;
    const int slot = tid / TPF;
    const int ltid = tid % TPF;
    const int base = slot * NFFT;

    auto sw = [](int i) { return swz<S>(i); };

    // Frame-scoped sync.
    auto fsync = [&]() {
        if constexpr (TPF <= 32) { __syncwarp(); }
        else if constexpr (TPF >= TPB) { __syncthreads(); }
        else { asm volatile("bar.sync %0, %1;" :: "r"(slot + 1), "r"(TPF) : "memory"); }
    };

    // Twiddles: tw[t] = exp(-2*pi*i*t/N). Window: periodic hann / sqrt(0.375*N).
    const float rnorm = rsqrtf(0.375f * (float)NFFT);
    for (int t = tid; t < NFFT / 2; t += TPB) {
        float s, c;
        sincospif(2.0f * (float)t / (float)NFFT, &s, &c);
        tw[t] = make_float2(c, -s);
    }
    for (int t = tid; t < NFFT; t += TPB) {
        win[t] = (0.5f - 0.5f * cospif(2.0f * (float)t / (float)NFFT)) * rnorm;
    }
    for (int t = tid; t < F; t += TPB) { red1[t] = 0.0f; red2[t] = 0.0f; }

    float acc1[KPT], acc2[KPT];
#pragma unroll
    for (int r = 0; r < KPT; r++) { acc1[r] = 0.0f; acc2[r] = 0.0f; }

    __syncthreads();

    for (int fb = blk * FPB; fb < TOTAL; fb += BLKS_PER_SCALE * FPB) {
        const int gf = fb + slot;
        const bool valid = (gf < TOTAL);

        // Load + window + 8-point DFT (stages 2,4,8 with trivial twiddles).
        // Thread reads samples idx + m*N/8 (coalesced), writes 8 consecutive
        // outputs at group g = bitrev_{LOG2N-3}(idx).
        if (valid) {
            const int bb = gf / T;
            const int t0 = gf - bb * T;
            const int start = t0 * HOP - PAD;
            const float* xb  = x  + bb * NSAMP;
            const float* xhb = xh + bb * NSAMP;
            const int idx = ltid;                 // [0, N/8), TPF == N/8
            const int g   = (int)(__brev((unsigned)idx) >> (32 - (LOG2N - 3)));
            float2 a[8];
#pragma unroll
            for (int m = 0; m < 8; m++) {
                const int tt = idx + m * (NFFT / 8);
                int s = start + tt;
                s = (s < 0) ? -s : s;                        // reflect left
                s = (s >= NSAMP) ? (2 * NSAMP - 2 - s) : s;  // reflect right
                const float wv = win[tt];
                a[m] = make_float2(xb[s] * wv, xhb[s] * wv);
            }
            // E = DFT4(a0,a2,a4,a6), O = DFT4(a1,a3,a5,a7)
            const float2 t0v = cadd(a[0], a[4]), t1v = csub(a[0], a[4]);
            const float2 t2v = cadd(a[2], a[6]), t3v = csub(a[2], a[6]);
            const float2 E0 = cadd(t0v, t2v), E2 = csub(t0v, t2v);
            const float2 E1 = make_float2(t1v.x + t3v.y, t1v.y - t3v.x);
            const float2 E3 = make_float2(t1v.x - t3v.y, t1v.y + t3v.x);
            const float2 u0 = cadd(a[1], a[5]), u1 = csub(a[1], a[5]);
            const float2 u2 = cadd(a[3], a[7]), u3 = csub(a[3], a[7]);
            const float2 O0 = cadd(u0, u2), O2 = csub(u0, u2);
            const float2 O1 = make_float2(u1.x + u3.y, u1.y - u3.x);
            const float2 O3 = make_float2(u1.x - u3.y, u1.y + u3.x);
            const float2 w1O1 = make_float2(RQ * (O1.x + O1.y), RQ * (O1.y - O1.x));   // (1-i)r*O1
            const float2 w2O2 = make_float2(O2.y, -O2.x);                               // -i*O2
            const float2 w3O3 = make_float2(RQ * (O3.y - O3.x), -RQ * (O3.x + O3.y));  // (-1-i)r*O3
            const int wb = base + 8 * g;
            buf[sw(wb + 0)] = cadd(E0, O0);   buf[sw(wb + 4)] = csub(E0, O0);
            buf[sw(wb + 1)] = cadd(E1, w1O1); buf[sw(wb + 5)] = csub(E1, w1O1);
            buf[sw(wb + 2)] = cadd(E2, w2O2); buf[sw(wb + 6)] = csub(E2, w2O2);
            buf[sw(wb + 3)] = cadd(E3, w3O3); buf[sw(wb + 7)] = csub(E3, w3O3);
        }
        fsync();

        // Remaining stages: radix-8 / radix-4 passes.
        if constexpr (LOG2N == 5) {
            radix4_pass<NFFT, 16, TPF, S>(buf, tw, base, ltid); fsync();
        } else if constexpr (LOG2N == 6) {
            radix8_pass<NFFT, 16, TPF, S>(buf, tw, base, ltid); fsync();
        } else if constexpr (LOG2N == 7) {
            radix4_pass<NFFT, 16, TPF, S>(buf, tw, base, ltid); fsync();
            radix4_pass<NFFT, 64, TPF, S>(buf, tw, base, ltid); fsync();
        } else if constexpr (LOG2N == 8) {
            radix8_pass<NFFT, 16, TPF, S>(buf, tw, base, ltid); fsync();
            radix4_pass<NFFT, 128, TPF, S>(buf, tw, base, ltid); fsync();
        } else if constexpr (LOG2N == 9) {
            radix8_pass<NFFT, 16, TPF, S>(buf, tw, base, ltid); fsync();
            radix8_pass<NFFT, 128, TPF, S>(buf, tw, base, ltid); fsync();
        } else if constexpr (LOG2N == 10) {
            radix8_pass<NFFT, 16, TPF, S>(buf, tw, base, ltid); fsync();
            radix4_pass<NFFT, 128, TPF, S>(buf, tw, base, ltid); fsync();
            radix4_pass<NFFT, 512, TPF, S>(buf, tw, base, ltid); fsync();
        } else {
            radix8_pass<NFFT, 16, TPF, S>(buf, tw, base, ltid); fsync();
            radix8_pass<NFFT, 128, TPF, S>(buf, tw, base, ltid); fsync();
            radix4_pass<NFFT, 1024, TPF, S>(buf, tw, base, ltid); fsync();
        }

        // Unpack X (from x) and Xh (from x_hat), accumulate stats
        if (valid) {
#pragma unroll
            for (int r = 0; r < KPT; r++) {
                const int k = ltid + r * TPF;
                if (k <= NFFT / 2) {
                    const float2 zk = buf[sw(base + k)];
                    const float2 zn = buf[sw(base + ((NFFT - k) & (NFFT - 1)))];
                    const float ar = 0.5f * (zk.x + zn.x);
                    const float ai = 0.5f * (zk.y - zn.y);
                    const float br = 0.5f * (zk.y + zn.y);
                    const float bi = 0.5f * (zn.x - zk.x);
                    const float magA = sqrtf(ar * ar + ai * ai);
                    const float magB = sqrtf(br * br + bi * bi);
                    const float d = magB - magA;          // |Xh| - |X|
                    acc1[r] += fabsf(d);
                    acc2[r] += d * d;
                }
            }
        }
        fsync();   // protect buf before next load (frame-scoped)
    }

    // Block reduce: registers -> shared float
#pragma unroll
    for (int r = 0; r < KPT; r++) {
        const int k = ltid + r * TPF;
        if (k <= NFFT / 2) {
            atomicAdd(&red1[k], acc1[r]);
            atomicAdd(&red2[k], acc2[r]);
        }
    }
    __syncthreads();

    for (int k = tid; k < F; k += TPB) {
        atomicAdd(&g_s1[OFF + k], (double)red1[k]);
        atomicAdd(&g_s2[OFF + k], (double)red2[k]);
    }
}

// All 7 scales in one launch; min 4 blocks/SM (forces <=64 regs, occ ~50%).
__global__ void __launch_bounds__(256, 4)
fused_stft(const float* __restrict__ x, const float* __restrict__ xh) {
    extern __shared__ char raw[];
    const int b = blockIdx.x;
    if      (b < 1 * BLKS_PER_SCALE) stft_body<  32,    0>(x, xh, b - 0 * BLKS_PER_SCALE, raw);
    else if (b < 2 * BLKS_PER_SCALE) stft_body<  64,   17>(x, xh, b - 1 * BLKS_PER_SCALE, raw);
    else if (b < 3 * BLKS_PER_SCALE) stft_body< 128,   50>(x, xh, b - 2 * BLKS_PER_SCALE, raw);
    else if (b < 4 * BLKS_PER_SCALE) stft_body< 256,  115>(x, xh, b - 3 * BLKS_PER_SCALE, raw);
    else if (b < 5 * BLKS_PER_SCALE) stft_body< 512,  244>(x, xh, b - 4 * BLKS_PER_SCALE, raw);
    else if (b < 6 * BLKS_PER_SCALE) stft_body<1024,  501>(x, xh, b - 5 * BLKS_PER_SCALE, raw);
    else                             stft_body<2048, 1014>(x, xh, b - 6 * BLKS_PER_SCALE, raw);
}

// ---------------------------------------------------------------------------
// Loss: 7 blocks (one per scale). f_pts is scale-independent and only 66
// distinct values are needed -> threads 0-65 each compute ONE libdevice pow
// into shared (vs 5 serial chains/thread before; this was 20us of FP64-pipe
// serialization). Band edges then use cheap compares on the table. The
// decision logic stays bit-identical (opaque(A)/2595 == opaque(A/2595) in
// exact bits, so f[65] equals the old hi65; Nyquist flip preserved).
// ---------------------------------------------------------------------------
__global__ void __launch_bounds__(256) loss_kernel(float* out) {
    const int s    = blockIdx.x;
    const int tid  = threadIdx.x;
    const int w    = tid >> 5;
    const int lane = tid & 31;
    const int NFFT = 32 << s;
    const int F    = NFFT / 2 + 1;

    __shared__ double fpts[66];
    __shared__ int2   sab[64];
    __shared__ double ssum;
    if (tid == 0) ssum = 0.0;

    const double melmax = 2595.0 * log10(1.0 + 12000.0 / 700.0);
    if (tid < 66) {
        fpts[tid] = 700.0 * (pow(10.0, opaque_d(melmax * (double)tid / 65.0) / 2595.0) - 1.0);
    }
    __syncthreads();

    bool keep = false;
    if (tid < 64) {
        const int m = tid;
        const double step = 12000.0 / (double)(F - 1);
        const bool nyq_in = !(fpts[65] > 12000.0);   // flipped libdevice decision (verified)

        int a[2], b[2];   // [0] = band m, [1] = band m-1
        for (int q = 0; q < 2; q++) {
            const int mm = m - q;
            if (mm < 0) { a[q] = 0; b[q] = 0; continue; }
            const double lo = fpts[mm];
            int a0 = (int)floor(lo / step); if ((double)a0 * step <= lo) a0++;  // first f: f*step > lo
            if (a0 < 0) a0 = 0;
            int b0;
            if (mm + 2 == 65) {
                b0 = nyq_in ? F : (F - 1);
            } else {
                const double hi = fpts[mm + 2];
                b0 = (int)floor(hi / step); if ((double)b0 * step <  hi) b0++;  // last f+1: f*step < hi
                if (b0 > F) b0 = F;
            }
            a[q] = a0; b[q] = b0;
        }
        const bool nonempty = (b[0] > a[0]);
        const bool dup = (m > 0) && (a[0] == a[1]) && (b[0] == b[1]) && nonempty;
        keep = nonempty && !dup;
        sab[m] = keep ? make_int2(a[0], b[0]) : make_int2(0, 0);
    }
    const int nb = __syncthreads_count(keep ? 1 : 0);

    for (int cand = w; cand < 64; cand += 8) {
        const int2 ab = sab[cand];
        if (ab.y > ab.x) {
            double p1 = 0.0, p2 = 0.0;
            for (int f = ab.x + lane; f < ab.y; f += 32) {
                p1 += g_s1[c_soff[s] + f];
                p2 += g_s2[c_soff[s] + f];
            }
#pragma unroll
            for (int o = 16; o > 0; o >>= 1) {
                p1 += __shfl_down_sync(0xffffffffu, p1, o);
                p2 += __shfl_down_sync(0xffffffffu, p2, o);
            }
            if (lane == 0) {
                const double cnt = (double)(ab.y - ab.x) * (double)BATCH * (double)c_T[s];
                const double val = p1 / cnt + sqrt(p2 / cnt + 1e-8);
                atomicAdd(&ssum, val);
            }
        }
    }
    __syncthreads();

    if (tid == 0) {
        double* acc  = g_blob + 2 * TOTF;
        int*    done = (int*)(g_blob + 2 * TOTF + 1);
        const double contrib = ssum / (double)nb / 7.0;
        atomicAdd(acc, contrib);
        __threadfence();
        const int old = atomicAdd(done, 1);
        if (old == 6) {
            out[0] = (float)(*(volatile double*)acc);
        }
    }
}

extern "C" void kernel_launch(void* const* d_in, const int* in_sizes, int n_in,
                              void* d_out, int out_size) {
    const float* xh = (const float*)d_in[0];   // x_hat
    const float* x  = (const float*)d_in[1];   // x

    void* pb = nullptr;
    cudaGetSymbolAddress(&pb, g_blob);
    cudaMemsetAsync(pb, 0, (2 * TOTF + 2) * sizeof(double));

    fused_stft<<<7 * BLKS_PER_SCALE, 256, SMEM_DYN>>>(x, xh);
    loss_kernel<<<7, 256>>>((float*)d_out);
}